// round 2
// baseline (speedup 1.0000x reference)
#include <cuda_runtime.h>
#include <cuda_bf16.h>
#include <cstdint>

// Problem constants (TMDLayer): B=8, N=2048, F=256, L=16, EPS=0.25
#define BB 8
#define NN 2048
#define FF 256
#define LL 16
#define EPSV 0.25f

typedef unsigned long long ull;

// ---------------- device scratch ----------------
__device__ float g_z[BB * NN * LL];   // projected z  [B,N,L]
__device__ float g_sq[BB * NN];       // |z|^2
__device__ float g_pi[BB * NN];       // pi(z)
__device__ float g_c[BB * NN];        // pi/q

// ---------------- helpers ----------------
__device__ __forceinline__ void cp_async16(void* dst_smem, const void* src_gmem) {
    unsigned s = (unsigned)__cvta_generic_to_shared(dst_smem);
    asm volatile("cp.async.cg.shared.global [%0], [%1], 16;\n" :: "r"(s), "l"(src_gmem));
}
__device__ __forceinline__ void cp_async_commit() {
    asm volatile("cp.async.commit_group;\n");
}
__device__ __forceinline__ void cp_async_wait_all() {
    asm volatile("cp.async.wait_group 0;\n");
}

// packed fp32x2 FMA: d = a*b + c (elementwise on 2 lanes)
__device__ __forceinline__ ull ffma2(ull a, ull b, ull c) {
    ull d;
    asm("fma.rn.f32x2 %0, %1, %2, %3;" : "=l"(d) : "l"(a), "l"(b), "l"(c));
    return d;
}
union F2U { ull u; float2 f; };
__device__ __forceinline__ float hadd2(ull v) {
    F2U t; t.u = v;
    return t.f.x + t.f.y;
}

// =====================================================================
// Kernel 1a: z = x @ proj_w^T + proj_b ; sq = |z|^2
// Block: 256 threads handles 16 points. Grid: B*N/16 = 1024.
// =====================================================================
__global__ void __launch_bounds__(256) k_proj(const float* __restrict__ x,
                                              const float* __restrict__ pw,
                                              const float* __restrict__ pb) {
    __shared__ __align__(16) float xs[16][260];
    __shared__ __align__(16) float pws[16][258];
    __shared__ float red[16][17];

    const int tid = threadIdx.x;
    const int p0 = blockIdx.x * 16;
    const float* xbase = x + (size_t)p0 * FF;

    for (int i = tid; i < 16 * 64; i += 256) {
        int r = i >> 6, c = (i & 63) << 2;
        float4 v = *reinterpret_cast<const float4*>(xbase + r * FF + c);
        *reinterpret_cast<float4*>(&xs[r][c]) = v;
    }
    for (int i = tid; i < LL * FF; i += 256) pws[i >> 8][i & 255] = pw[i];
    __syncthreads();

    const int n = tid >> 4;
    const int l = tid & 15;
    // packed dot over F=256 (128 pairs)
    ull a2 = 0ULL;
#pragma unroll 8
    for (int f2 = 0; f2 < FF / 2; f2++) {
        ull xv = *reinterpret_cast<const ull*>(&xs[n][f2 << 1]);
        ull wv = *reinterpret_cast<const ull*>(&pws[l][f2 << 1]);
        a2 = ffma2(xv, wv, a2);
    }
    float acc = hadd2(a2) + pb[l];

    g_z[(size_t)(p0 + n) * LL + l] = acc;
    red[n][l] = acc * acc;
    __syncthreads();
    if (l == 0) {
        float s = 0.f;
#pragma unroll
        for (int j = 0; j < LL; j++) s += red[n][j];
        g_sq[p0 + n] = s;
    }
}

// =====================================================================
// Kernel 1b: pi = sigmoid( relu(z @ w1^T + b1) @ w2^T + b2 )
// 128 points per block, 2 threads per point (f-split), shuffle combine.
// Grid: B*N/128 = 128 blocks of 256 threads.
// =====================================================================
__global__ void __launch_bounds__(256) k_pi(const float* __restrict__ w1,
                                            const float* __restrict__ b1,
                                            const float* __restrict__ w2,
                                            const float* __restrict__ b2) {
    __shared__ __align__(16) float zs[128][18];
    __shared__ __align__(16) float w1s[256][16];   // [f][l], rows 64B aligned
    __shared__ float b1s[256];
    __shared__ float w2s[256];

    const int tid = threadIdx.x;
    const int p0 = blockIdx.x * 128;

    for (int i = tid; i < 128 * LL; i += 256) zs[i >> 4][i & 15] = g_z[(size_t)p0 * LL + i];
    for (int i = tid; i < FF * LL; i += 256) w1s[i >> 4][i & 15] = w1[i];
    b1s[tid] = b1[tid];
    w2s[tid] = w2[tid];
    __syncthreads();

    const int p = tid >> 1;        // local point
    const int h = tid & 1;         // f-half
    ull zp[8];
#pragma unroll
    for (int l2 = 0; l2 < 8; l2++) zp[l2] = *reinterpret_cast<const ull*>(&zs[p][l2 << 1]);

    float accum = 0.f;
    const int f0 = h * 128;
#pragma unroll 4
    for (int fo = 0; fo < 128; fo++) {
        const int f = f0 + fo;
        ull d2 = 0ULL;
#pragma unroll
        for (int l2 = 0; l2 < 8; l2++) {
            ull wv = *reinterpret_cast<const ull*>(&w1s[f][l2 << 1]);
            d2 = ffma2(zp[l2], wv, d2);
        }
        float hv = hadd2(d2) + b1s[f];
        hv = fmaxf(hv, 0.f);
        accum = fmaf(hv, w2s[f], accum);
    }
    accum += __shfl_xor_sync(0xffffffffu, accum, 1);
    if (h == 0) {
        float t = accum + b2[0];
        g_pi[p0 + p] = 1.0f / (1.0f + __expf(-t));
    }
}

// =====================================================================
// Kernel 2: q[n] = sum_m exp(-d2(n,m)) ; c = pi/q
// Block: 256 threads = 32 rows x 8 m-lanes. Grid: (N/32, B).
// =====================================================================
__global__ void __launch_bounds__(256) k_q(void) {
    __shared__ __align__(16) float znS[32][18];
    __shared__ float sqnS[32];
    __shared__ __align__(16) float zmS[256][18];
    __shared__ float sqmS[256];

    const int tid = threadIdx.x;
    const int b = blockIdx.y;
    const int n0 = blockIdx.x * 32;
    const float* zb = g_z + (size_t)b * NN * LL;
    const float* sqb = g_sq + (size_t)b * NN;

    for (int i = tid; i < 32 * LL; i += 256) znS[i >> 4][i & 15] = zb[(size_t)n0 * LL + i];
    if (tid < 32) sqnS[tid] = sqb[n0 + tid];
    __syncthreads();

    const int n = tid >> 3;
    const int j = tid & 7;
    ull znp[8];
#pragma unroll
    for (int l2 = 0; l2 < 8; l2++) znp[l2] = *reinterpret_cast<const ull*>(&znS[n][l2 << 1]);
    const float sqn_r = sqnS[n];
    const float kscale = 1.0f / (4.0f * EPSV);

    float qacc = 0.f;
    for (int t = 0; t < NN / 256; t++) {
        __syncthreads();
        for (int i = tid; i < 256 * LL; i += 256) zmS[i >> 4][i & 15] = zb[(size_t)(t * 256) * LL + i];
        sqmS[tid] = sqb[t * 256 + tid];
        __syncthreads();
#pragma unroll 4
        for (int mm = j; mm < 256; mm += 8) {
            ull d64 = 0ULL;
#pragma unroll
            for (int l2 = 0; l2 < 8; l2++)
                d64 = ffma2(znp[l2], *reinterpret_cast<const ull*>(&zmS[mm][l2 << 1]), d64);
            float dot = hadd2(d64);
            float d2 = fmaxf(sqn_r + sqmS[mm] - 2.0f * dot, 0.f);
            qacc += __expf(-d2 * kscale);
        }
    }
#pragma unroll
    for (int o = 4; o > 0; o >>= 1) qacc += __shfl_down_sync(0xffffffffu, qacc, o, 8);
    if (j == 0) {
        int idx = b * NN + n0 + n;
        g_c[idx] = g_pi[idx] / qacc;
    }
}

// =====================================================================
// Kernel 3 (dominant): fused K-recompute + (K*c)@x + rowsum + epilogue
// Stage-2 GEMM in packed fp32x2 (FFMA2). w stored duplicated as float2.
// Block: 256 threads, 32 rows x F=256. Grid: (N/32, B).
// =====================================================================
struct __align__(16) K3Smem {
    float xs[64][256];       // 65536 B
    float zm[64][18];        // 4608  (8B-aligned rows)
    float zn[32][18];        // 2304
    float2 w2[64][33];       // 16896  w2[m][n] = {w,w}
    float cm[64];
    float sqm[64];
    float sqn[32];
    float rsred[32][8];
    float rowscale[32];
};

__global__ void __launch_bounds__(256, 2) k_main(const float* __restrict__ x,
                                                 float* __restrict__ out,
                                                 const float* __restrict__ dtp) {
    extern __shared__ char smem_raw[];
    K3Smem& S = *reinterpret_cast<K3Smem*>(smem_raw);

    const int tid = threadIdx.x;
    const int b = blockIdx.y;
    const int n0 = blockIdx.x * 32;
    const float* xb = x + (size_t)b * NN * FF;
    const float* zb = g_z + (size_t)b * NN * LL;
    const float* sqb = g_sq + (size_t)b * NN;
    const float* cb = g_c + (size_t)b * NN;

    for (int i = tid; i < 32 * LL; i += 256) S.zn[i >> 4][i & 15] = zb[(size_t)n0 * LL + i];
    if (tid < 32) S.sqn[tid] = sqb[n0 + tid];
    __syncthreads();

    // stage-1 identity: row ns (lane), m-group mg (warp)
    const int ns = tid & 31;
    const int mg = tid >> 5;
    ull znp[8];
#pragma unroll
    for (int l2 = 0; l2 < 8; l2++) znp[l2] = *reinterpret_cast<const ull*>(&S.zn[ns][l2 << 1]);
    const float sqn_r = S.sqn[ns];
    const float kscale = 1.0f / (4.0f * EPSV);

    // stage-2 identity: f-quad fq, row-group rg
    const int fq = tid & 63;
    const int rg = tid >> 6;
    ull acc[8][2];                 // 8 rows x 4 f (2 packed pairs)
#pragma unroll
    for (int k = 0; k < 8; k++) { acc[k][0] = 0ULL; acc[k][1] = 0ULL; }
    float rs = 0.f;

    for (int mt = 0; mt < NN / 64; mt++) {
        const int m0 = mt * 64;
        {   // async-fill x tile [64][256]
            const float* src = xb + (size_t)m0 * FF;
            for (int i = tid; i < 64 * 64; i += 256) {
                int r = i >> 6, c = (i & 63) << 2;
                cp_async16(&S.xs[r][c], src + r * FF + c);
            }
            cp_async_commit();
        }
        for (int i = tid; i < 64 * LL; i += 256) S.zm[i >> 4][i & 15] = zb[(size_t)m0 * LL + i];
        if (tid < 64) {
            S.cm[tid] = cb[m0 + tid];
            S.sqm[tid] = sqb[m0 + tid];
        }
        __syncthreads();

        // stage 1: w2[m][n] = {wv,wv}, wv = exp(-d2)*c[m]   (packed dot)
#pragma unroll
        for (int j = 0; j < 8; j++) {
            const int m = mg * 8 + j;
            ull d64 = 0ULL;
#pragma unroll
            for (int l2 = 0; l2 < 8; l2++)
                d64 = ffma2(znp[l2], *reinterpret_cast<const ull*>(&S.zm[m][l2 << 1]), d64);
            float dot = hadd2(d64);
            float d2 = fmaxf(sqn_r + S.sqm[m] - 2.0f * dot, 0.f);
            float wv = __expf(-d2 * kscale) * S.cm[m];
            S.w2[m][ns] = make_float2(wv, wv);
            rs += wv;
        }
        cp_async_wait_all();
        __syncthreads();

        // stage 2: acc += w (x) x   -- all packed f32x2
#pragma unroll 4
        for (int m = 0; m < 64; m++) {
            ulonglong2 xv = *reinterpret_cast<const ulonglong2*>(&S.xs[m][fq << 2]);
#pragma unroll
            for (int k = 0; k < 8; k++) {
                const ull wv = *reinterpret_cast<const ull*>(&S.w2[m][rg * 8 + k]);
                acc[k][0] = ffma2(wv, xv.x, acc[k][0]);
                acc[k][1] = ffma2(wv, xv.y, acc[k][1]);
            }
        }
        __syncthreads();
    }

    // rowsum reduction
    S.rsred[ns][mg] = rs;
    __syncthreads();
    const float dtv = dtp[0];
    if (tid < 32) {
        float r = 1e-5f;
#pragma unroll
        for (int g = 0; g < 8; g++) r += S.rsred[tid][g];
        S.rowscale[tid] = (dtv / EPSV) / r;
    }
    __syncthreads();

    const float omdt = 1.0f - dtv;
    float* ob = out + (size_t)b * NN * FF;
#pragma unroll
    for (int k = 0; k < 8; k++) {
        const int r = rg * 8 + k;
        const int n = n0 + r;
        const float sc = S.rowscale[r];
        float4 xv = *reinterpret_cast<const float4*>(xb + (size_t)n * FF + (fq << 2));
        F2U a0, a1; a0.u = acc[k][0]; a1.u = acc[k][1];
        float4 o;
        o.x = omdt * xv.x + sc * a0.f.x;
        o.y = omdt * xv.y + sc * a0.f.y;
        o.z = omdt * xv.z + sc * a1.f.x;
        o.w = omdt * xv.w + sc * a1.f.y;
        *reinterpret_cast<float4*>(ob + (size_t)n * FF + (fq << 2)) = o;
    }
}

// =====================================================================
// launch
// =====================================================================
extern "C" void kernel_launch(void* const* d_in, const int* in_sizes, int n_in,
                              void* d_out, int out_size) {
    const float* x  = (const float*)d_in[0];
    const float* pw = (const float*)d_in[1];
    const float* pb = (const float*)d_in[2];
    const float* w1 = (const float*)d_in[3];
    const float* b1 = (const float*)d_in[4];
    const float* w2 = (const float*)d_in[5];
    const float* b2 = (const float*)d_in[6];
    const float* dt = (const float*)d_in[7];
    float* out = (float*)d_out;

    (void)in_sizes; (void)n_in; (void)out_size;

    const int npts = BB * NN;

    k_proj<<<npts / 16, 256>>>(x, pw, pb);
    k_pi<<<npts / 128, 256>>>(w1, b1, w2, b2);
    k_q<<<dim3(NN / 32, BB), 256>>>();

    static_assert(sizeof(K3Smem) <= 100 * 1024, "k3 smem too big");
    cudaFuncSetAttribute(k_main, cudaFuncAttributeMaxDynamicSharedMemorySize,
                         (int)sizeof(K3Smem));
    k_main<<<dim3(NN / 32, BB), 256, sizeof(K3Smem)>>>(x, out, dt);
}

// round 4
// speedup vs baseline: 2.7692x; 2.7692x over previous
#include <cuda_runtime.h>
#include <cuda_fp16.h>
#include <cstdint>

// Problem constants (TMDLayer): B=8, N=2048, F=256, L=16, EPS=0.25
#define BB 8
#define NN 2048
#define FF 256
#define LL 16
#define EPSV 0.25f
#define MTILES 32      // m-tiles of 64
#define TK 64          // m per tile

typedef unsigned long long ull;

// ---------------- device scratch ----------------
__device__ float g_z[BB * NN * LL];
__device__ float g_sq[BB * NN];
__device__ float g_pi[BB * NN];
__device__ float g_q[BB * NN];
__device__ float g_c[BB * NN];
// K as fp16, plain row-major [b][n][m]
__device__ __align__(128) __half g_K[(size_t)BB * NN * NN];
// y = c*x as fp16, transposed [b][f][m]
__device__ __align__(128) __half g_y[(size_t)BB * FF * NN];

// ---------------- helpers ----------------
__device__ __forceinline__ unsigned smem_u32(const void* p) {
    unsigned a;
    asm("{ .reg .u64 t; cvta.to.shared.u64 t, %1; cvt.u32.u64 %0, t; }" : "=r"(a) : "l"(p));
    return a;
}
__device__ __forceinline__ void cp_async16s(unsigned dst, const void* src) {
    asm volatile("cp.async.cg.shared.global [%0], [%1], 16;\n" :: "r"(dst), "l"(src));
}
__device__ __forceinline__ void cp_commit() { asm volatile("cp.async.commit_group;\n"); }
__device__ __forceinline__ void cp_wait0() { asm volatile("cp.async.wait_group 0;\n"); }
__device__ __forceinline__ void cp_wait1() { asm volatile("cp.async.wait_group 1;\n"); }

__device__ __forceinline__ ull ffma2(ull a, ull b, ull c) {
    ull d;
    asm("fma.rn.f32x2 %0, %1, %2, %3;" : "=l"(d) : "l"(a), "l"(b), "l"(c));
    return d;
}
union F2U { ull u; float2 f; };
__device__ __forceinline__ float hadd2(ull v) { F2U t; t.u = v; return t.f.x + t.f.y; }

__device__ __forceinline__ void mma16816(float* d, const uint32_t* a, const uint32_t* b) {
    asm volatile(
        "mma.sync.aligned.m16n8k16.row.col.f32.f16.f16.f32 "
        "{%0,%1,%2,%3}, {%4,%5,%6,%7}, {%8,%9}, {%0,%1,%2,%3};"
        : "+f"(d[0]), "+f"(d[1]), "+f"(d[2]), "+f"(d[3])
        : "r"(a[0]), "r"(a[1]), "r"(a[2]), "r"(a[3]), "r"(b[0]), "r"(b[1]));
}

// =====================================================================
// Kernel 1a: z = x @ proj_w^T + proj_b ; sq = |z|^2
// =====================================================================
__global__ void __launch_bounds__(256) k_proj(const float* __restrict__ x,
                                              const float* __restrict__ pw,
                                              const float* __restrict__ pb) {
    __shared__ __align__(16) float xs[16][260];
    __shared__ __align__(16) float pws[16][258];
    __shared__ float red[16][17];

    const int tid = threadIdx.x;
    const int p0 = blockIdx.x * 16;
    const float* xbase = x + (size_t)p0 * FF;

    for (int i = tid; i < 16 * 64; i += 256) {
        int r = i >> 6, c = (i & 63) << 2;
        float4 v = *reinterpret_cast<const float4*>(xbase + r * FF + c);
        *reinterpret_cast<float4*>(&xs[r][c]) = v;
    }
    for (int i = tid; i < LL * FF; i += 256) pws[i >> 8][i & 255] = pw[i];
    __syncthreads();

    const int n = tid >> 4;
    const int l = tid & 15;
    ull a2 = 0ULL;
#pragma unroll 8
    for (int f2 = 0; f2 < FF / 2; f2++) {
        ull xv = *reinterpret_cast<const ull*>(&xs[n][f2 << 1]);
        ull wv = *reinterpret_cast<const ull*>(&pws[l][f2 << 1]);
        a2 = ffma2(xv, wv, a2);
    }
    float acc = hadd2(a2) + pb[l];

    g_z[(size_t)(p0 + n) * LL + l] = acc;
    red[n][l] = acc * acc;
    __syncthreads();
    if (l == 0) {
        float s = 0.f;
#pragma unroll
        for (int j = 0; j < LL; j++) s += red[n][j];
        g_sq[p0 + n] = s;
    }
}

// =====================================================================
// Kernel 1b: pi = sigmoid( relu(z @ w1^T + b1) @ w2^T + b2 )
// =====================================================================
__global__ void __launch_bounds__(256) k_pi(const float* __restrict__ w1,
                                            const float* __restrict__ b1,
                                            const float* __restrict__ w2,
                                            const float* __restrict__ b2) {
    __shared__ __align__(16) float zs[128][18];
    __shared__ __align__(16) float w1s[256][16];
    __shared__ float b1s[256];
    __shared__ float w2s[256];

    const int tid = threadIdx.x;
    const int p0 = blockIdx.x * 128;

    for (int i = tid; i < 128 * LL; i += 256) zs[i >> 4][i & 15] = g_z[(size_t)p0 * LL + i];
    for (int i = tid; i < FF * LL; i += 256) w1s[i >> 4][i & 15] = w1[i];
    b1s[tid] = b1[tid];
    w2s[tid] = w2[tid];
    __syncthreads();

    const int p = tid >> 1;
    const int h = tid & 1;
    ull zp[8];
#pragma unroll
    for (int l2 = 0; l2 < 8; l2++) zp[l2] = *reinterpret_cast<const ull*>(&zs[p][l2 << 1]);

    float accum = 0.f;
    const int f0 = h * 128;
#pragma unroll 4
    for (int fo = 0; fo < 128; fo++) {
        const int f = f0 + fo;
        ull d2 = 0ULL;
#pragma unroll
        for (int l2 = 0; l2 < 8; l2++) {
            ull wv = *reinterpret_cast<const ull*>(&w1s[f][l2 << 1]);
            d2 = ffma2(zp[l2], wv, d2);
        }
        float hv = hadd2(d2) + b1s[f];
        hv = fmaxf(hv, 0.f);
        accum = fmaf(hv, w2s[f], accum);
    }
    accum += __shfl_xor_sync(0xffffffffu, accum, 1);
    if (h == 0) {
        float t = accum + b2[0];
        g_pi[p0 + p] = 1.0f / (1.0f + __expf(-t));
    }
}

// =====================================================================
// Kernel 2: K pass. q[n] = sum_m exp(-d2); store K fp16 row-major.
// Grid: (N/128, B), 256 threads = 128 rows x 2 m-halves.
// =====================================================================
__global__ void __launch_bounds__(256) k_K(void) {
    __shared__ __align__(16) float zm[TK][18];
    __shared__ float sqm[TK];
    __shared__ uint32_t Kt[128][33];      // [n][m-pair], pitch 33 words: conflict-free
    __shared__ float qp[128][2];

    const int tid = threadIdx.x;
    const int nb = blockIdx.x, b = blockIdx.y;
    const int n = tid & 127, mh = tid >> 7;
    const int gn = b * NN + nb * 128 + n;

    ull znp[8];
    {
        const float* zrow = g_z + (size_t)gn * LL;
#pragma unroll
        for (int l2 = 0; l2 < 8; l2++) {
            F2U u; u.f = *reinterpret_cast<const float2*>(zrow + l2 * 2);
            znp[l2] = u.u;
        }
    }
    const float sqn = g_sq[gn];
    float qacc = 0.f;

    const float* zb = g_z + (size_t)b * NN * LL;
    const float* sqb = g_sq + (size_t)b * NN;

    for (int mt = 0; mt < MTILES; mt++) {
        __syncthreads();
        for (int i = tid; i < TK * LL; i += 256) zm[i >> 4][i & 15] = zb[(size_t)(mt * TK) * LL + i];
        if (tid < TK) sqm[tid] = sqb[mt * TK + tid];
        __syncthreads();

        float prev = 0.f;
#pragma unroll
        for (int j = 0; j < 32; j++) {
            const int m = mh * 32 + j;
            ull d64 = 0ULL;
#pragma unroll
            for (int l2 = 0; l2 < 8; l2++)
                d64 = ffma2(znp[l2], *reinterpret_cast<const ull*>(&zm[m][l2 << 1]), d64);
            float dot = hadd2(d64);
            float d2 = fmaxf(sqn + sqm[m] - 2.0f * dot, 0.f);
            float kv = __expf(-d2);          // 1/(4*eps) = 1
            qacc += kv;
            if (j & 1) {
                __half2 hv = __floats2half2_rn(prev, kv);
                Kt[n][mh * 16 + (j >> 1)] = *reinterpret_cast<uint32_t*>(&hv);
            } else {
                prev = kv;
            }
        }
        __syncthreads();
        // coalesced writeout: 128 rows x 32 words
        uint32_t* gK = reinterpret_cast<uint32_t*>(
            g_K + ((size_t)(b * NN + nb * 128) * NN + mt * TK));
        const unsigned roww = NN / 2;
        for (int i = tid; i < 128 * 32; i += 256)
            gK[(size_t)(i >> 5) * roww + (i & 31)] = Kt[i >> 5][i & 31];
    }
    qp[n][mh] = qacc;
    __syncthreads();
    if (tid < 128) g_q[b * NN + nb * 128 + tid] = qp[tid][0] + qp[tid][1];
}

// =====================================================================
// Kernel 3: c = pi/q ; y[f][m] = c[m]*x[m][f] fp16 (transposed).
// Grid: (MTILES, B), 256 threads (one per f).
// =====================================================================
__global__ void __launch_bounds__(256) k_y(const float* __restrict__ x) {
    __shared__ float cs[TK];
    __shared__ uint32_t yt[256][33];

    const int tid = threadIdx.x;
    const int mt = blockIdx.x, b = blockIdx.y;
    const float* xb = x + ((size_t)b * NN + mt * TK) * FF;

    if (tid < TK) {
        int gm = b * NN + mt * TK + tid;
        float c = g_pi[gm] / g_q[gm];
        g_c[gm] = c;
        cs[tid] = c;
    }
    __syncthreads();

    const int f = tid;
#pragma unroll 8
    for (int j = 0; j < 32; j++) {
        float y0 = cs[2 * j]     * __ldg(xb + (size_t)(2 * j) * FF + f);
        float y1 = cs[2 * j + 1] * __ldg(xb + (size_t)(2 * j + 1) * FF + f);
        __half2 hv = __floats2half2_rn(y0, y1);
        yt[f][j] = *reinterpret_cast<uint32_t*>(&hv);
    }
    __syncthreads();
    uint32_t* gY = reinterpret_cast<uint32_t*>(g_y + ((size_t)b * FF * NN + mt * TK));
    const unsigned roww = NN / 2;
    for (int i = tid; i < 256 * 32; i += 256)
        gY[(size_t)(i >> 5) * roww + (i & 31)] = yt[i >> 5][i & 31];
}

// =====================================================================
// Kernel 4: HMMA GEMM. out-tile 64 rows x 256 cols per CTA.
// 8 warps (2m x 4n), warp tile 32x64, k-tile 64, double-buffered cp.async.
// D = K @ y^T (both fp16, fp32 acc), rowsum FFMA, fused epilogue.
// =====================================================================
#define APITCH 72              // halves (144B)
#define ABYTES (64 * 144)      // 9216
#define BBYTES (256 * 144)     // 36864
#define BUFBYTES (ABYTES + BBYTES)   // 46080
#define OFF_C  (2 * BUFBYTES)        // 92160: 2 x 64 floats
#define OFF_RS (OFF_C + 512)         // 92672: 64 x 4 floats
#define OFF_SC (OFF_RS + 1024)       // 93696: 64 floats
#define SMEM_TOTAL (OFF_SC + 256)    // 93952

__global__ void __launch_bounds__(256, 2)
k_main(const float* __restrict__ x, float* __restrict__ out,
       const float* __restrict__ dtp) {
    extern __shared__ __align__(16) unsigned char sm[];
    const unsigned smb = smem_u32(sm);

    const int tid = threadIdx.x;
    const int nb = blockIdx.x, b = blockIdx.y;
    const int wid = tid >> 5, lane = tid & 31;
    const int g = lane >> 2, q = lane & 3;          // mma group / thread-in-group
    const int wm = wid & 1, wn = wid >> 1;          // warp grid 2m x 4n

    const __half* Kg = g_K + (size_t)(b * NN + nb * 64) * NN;
    const __half* Yg = g_y + (size_t)b * FF * NN;
    const float* cg = g_c + (size_t)b * NN;

    auto fill = [&](int t, int buf) {
        const unsigned base = smb + buf * BUFBYTES;
        const __half* aG = Kg + t * TK;
        const __half* bG = Yg + t * TK;
        for (int i = tid; i < 512; i += 256)
            cp_async16s(base + (i >> 3) * 144 + (i & 7) * 16,
                        aG + (size_t)(i >> 3) * NN + (i & 7) * 8);
        for (int i = tid; i < 2048; i += 256)
            cp_async16s(base + ABYTES + (i >> 3) * 144 + (i & 7) * 16,
                        bG + (size_t)(i >> 3) * NN + (i & 7) * 8);
        if (tid < 16)
            cp_async16s(smb + OFF_C + buf * 256 + tid * 16, cg + t * TK + tid * 4);
        cp_commit();
    };

    fill(0, 0);
    fill(1, 1);

    float acc[2][8][4];
#pragma unroll
    for (int mf = 0; mf < 2; mf++)
#pragma unroll
        for (int nf = 0; nf < 8; nf++)
#pragma unroll
            for (int k = 0; k < 4; k++) acc[mf][nf][k] = 0.f;
    float rs = 0.f;
    const int rn = tid & 63, qm = tid >> 6;     // rowsum identity

    for (int t = 0; t < MTILES; t++) {
        const int buf = t & 1;
        if (t < MTILES - 1) cp_wait1(); else cp_wait0();
        __syncthreads();

        const __half* Ks = reinterpret_cast<const __half*>(sm + buf * BUFBYTES);
        const __half* Ys = reinterpret_cast<const __half*>(sm + buf * BUFBYTES + ABYTES);

        // rowsum partial: thread (rn, qm) covers 16 m
        {
            const float* cP = reinterpret_cast<const float*>(sm + OFF_C + buf * 256);
#pragma unroll
            for (int j = 0; j < 8; j++) {
                __half2 hv = *reinterpret_cast<const __half2*>(Ks + rn * APITCH + qm * 16 + 2 * j);
                float2 fv = __half22float2(hv);
                rs = fmaf(fv.x, cP[qm * 16 + 2 * j], rs);
                rs = fmaf(fv.y, cP[qm * 16 + 2 * j + 1], rs);
            }
        }

        // HMMA: warp tile 32m x 64n, k = 64 in 4 steps of 16
#pragma unroll
        for (int ks = 0; ks < 4; ks++) {
            const int k0 = ks * 16;
            uint32_t bf[8][2];
#pragma unroll
            for (int nf = 0; nf < 8; nf++) {
                const int n = wn * 64 + nf * 8 + g;
                bf[nf][0] = *reinterpret_cast<const uint32_t*>(Ys + n * APITCH + k0 + 2 * q);
                bf[nf][1] = *reinterpret_cast<const uint32_t*>(Ys + n * APITCH + k0 + 2 * q + 8);
            }
            uint32_t af[2][4];
#pragma unroll
            for (int mf = 0; mf < 2; mf++) {
                const int r = wm * 32 + mf * 16 + g;
                af[mf][0] = *reinterpret_cast<const uint32_t*>(Ks + r * APITCH + k0 + 2 * q);
                af[mf][1] = *reinterpret_cast<const uint32_t*>(Ks + (r + 8) * APITCH + k0 + 2 * q);
                af[mf][2] = *reinterpret_cast<const uint32_t*>(Ks + r * APITCH + k0 + 2 * q + 8);
                af[mf][3] = *reinterpret_cast<const uint32_t*>(Ks + (r + 8) * APITCH + k0 + 2 * q + 8);
            }
#pragma unroll
            for (int mf = 0; mf < 2; mf++)
#pragma unroll
                for (int nf = 0; nf < 8; nf++)
                    mma16816(acc[mf][nf], af[mf], bf[nf]);
        }
        __syncthreads();
        if (t + 2 < MTILES) fill(t + 2, buf);
    }

    // rowsum reduce -> rowscale
    reinterpret_cast<float*>(sm + OFF_RS)[rn * 4 + qm] = rs;
    __syncthreads();
    const float dtv = dtp[0];
    if (tid < 64) {
        const float* rp = reinterpret_cast<const float*>(sm + OFF_RS) + tid * 4;
        float row = rp[0] + rp[1] + rp[2] + rp[3] + 1e-5f;
        reinterpret_cast<float*>(sm + OFF_SC)[tid] = (dtv / EPSV) / row;
    }
    __syncthreads();

    // epilogue: out = (1-dt)*x + sc*acc
    const float omdt = 1.0f - dtv;
    const float* scS = reinterpret_cast<const float*>(sm + OFF_SC);
#pragma unroll
    for (int mf = 0; mf < 2; mf++) {
        const int lr = wm * 32 + mf * 16 + g;
        const float sc1 = scS[lr], sc2 = scS[lr + 8];
        const size_t r1 = (size_t)(b * NN + nb * 64 + lr) * FF;
        const size_t r2 = r1 + (size_t)8 * FF;
#pragma unroll
        for (int nf = 0; nf < 8; nf++) {
            const int col = wn * 64 + nf * 8 + 2 * q;
            float2 x1 = *reinterpret_cast<const float2*>(x + r1 + col);
            float2 x2 = *reinterpret_cast<const float2*>(x + r2 + col);
            float2 o1, o2;
            o1.x = omdt * x1.x + sc1 * acc[mf][nf][0];
            o1.y = omdt * x1.y + sc1 * acc[mf][nf][1];
            o2.x = omdt * x2.x + sc2 * acc[mf][nf][2];
            o2.y = omdt * x2.y + sc2 * acc[mf][nf][3];
            *reinterpret_cast<float2*>(out + r1 + col) = o1;
            *reinterpret_cast<float2*>(out + r2 + col) = o2;
        }
    }
}

// =====================================================================
// launch
// =====================================================================
extern "C" void kernel_launch(void* const* d_in, const int* in_sizes, int n_in,
                              void* d_out, int out_size) {
    const float* x  = (const float*)d_in[0];
    const float* pw = (const float*)d_in[1];
    const float* pb = (const float*)d_in[2];
    const float* w1 = (const float*)d_in[3];
    const float* b1 = (const float*)d_in[4];
    const float* w2 = (const float*)d_in[5];
    const float* b2 = (const float*)d_in[6];
    const float* dt = (const float*)d_in[7];
    float* out = (float*)d_out;

    (void)in_sizes; (void)n_in; (void)out_size;

    const int npts = BB * NN;

    k_proj<<<npts / 16, 256>>>(x, pw, pb);
    k_pi<<<npts / 128, 256>>>(w1, b1, w2, b2);
    k_K<<<dim3(NN / 128, BB), 256>>>();
    k_y<<<dim3(MTILES, BB), 256>>>(x);

    cudaFuncSetAttribute(k_main, cudaFuncAttributeMaxDynamicSharedMemorySize,
                         (int)SMEM_TOTAL);
    k_main<<<dim3(NN / 64, BB), 256, SMEM_TOTAL>>>(x, out, dt);
}

// round 5
// speedup vs baseline: 3.9910x; 1.4412x over previous
#include <cuda_runtime.h>
#include <cuda_fp16.h>
#include <cstdint>

// Problem constants (TMDLayer): B=8, N=2048, F=256, L=16, EPS=0.25
#define BB 8
#define NN 2048
#define FF 256
#define LL 16
#define EPSV 0.25f
#define MTILES 32      // m-tiles of 64 (k_main / k_y)
#define TK 64
#define NT 16          // k_K tiles of 128
#define NPAIRS 136     // NT*(NT+1)/2

typedef unsigned long long ull;

// ---------------- device scratch ----------------
__device__ float g_z[BB * NN * LL];
__device__ float g_sq[BB * NN];
__device__ float g_pi[BB * NN];
__device__ float g_c[BB * NN];
// q partial sums: slot s, row n — unique writer per (b,s,n), no atomics
__device__ float g_qpart[(size_t)BB * NT * NN];
// K as fp16, plain row-major [b][n][m]
__device__ __align__(128) __half g_K[(size_t)BB * NN * NN];
// y = c*x as fp16, transposed [b][f][m]
__device__ __align__(128) __half g_y[(size_t)BB * FF * NN];

// ---------------- helpers ----------------
__device__ __forceinline__ unsigned smem_u32(const void* p) {
    unsigned a;
    asm("{ .reg .u64 t; cvta.to.shared.u64 t, %1; cvt.u32.u64 %0, t; }" : "=r"(a) : "l"(p));
    return a;
}
__device__ __forceinline__ void cp_async16s(unsigned dst, const void* src) {
    asm volatile("cp.async.cg.shared.global [%0], [%1], 16;\n" :: "r"(dst), "l"(src));
}
__device__ __forceinline__ void cp_commit() { asm volatile("cp.async.commit_group;\n"); }
__device__ __forceinline__ void cp_wait0() { asm volatile("cp.async.wait_group 0;\n"); }
__device__ __forceinline__ void cp_wait1() { asm volatile("cp.async.wait_group 1;\n"); }

__device__ __forceinline__ ull ffma2(ull a, ull b, ull c) {
    ull d;
    asm("fma.rn.f32x2 %0, %1, %2, %3;" : "=l"(d) : "l"(a), "l"(b), "l"(c));
    return d;
}
union F2U { ull u; float2 f; };
__device__ __forceinline__ float hadd2(ull v) { F2U t; t.u = v; return t.f.x + t.f.y; }

__device__ __forceinline__ void mma16816(float* d, const uint32_t* a, const uint32_t* b) {
    asm volatile(
        "mma.sync.aligned.m16n8k16.row.col.f32.f16.f16.f32 "
        "{%0,%1,%2,%3}, {%4,%5,%6,%7}, {%8,%9}, {%0,%1,%2,%3};"
        : "+f"(d[0]), "+f"(d[1]), "+f"(d[2]), "+f"(d[3])
        : "r"(a[0]), "r"(a[1]), "r"(a[2]), "r"(a[3]), "r"(b[0]), "r"(b[1]));
}
__device__ __forceinline__ void ldsm4(uint32_t* r, unsigned addr) {
    asm volatile("ldmatrix.sync.aligned.m8n8.x4.shared.b16 {%0,%1,%2,%3}, [%4];"
        : "=r"(r[0]), "=r"(r[1]), "=r"(r[2]), "=r"(r[3]) : "r"(addr));
}

// =====================================================================
// Kernel 1a: z = x @ proj_w^T + proj_b ; sq = |z|^2
// =====================================================================
__global__ void __launch_bounds__(256) k_proj(const float* __restrict__ x,
                                              const float* __restrict__ pw,
                                              const float* __restrict__ pb) {
    __shared__ __align__(16) float xs[16][260];
    __shared__ __align__(16) float pws[16][258];
    __shared__ float red[16][17];

    const int tid = threadIdx.x;
    const int p0 = blockIdx.x * 16;
    const float* xbase = x + (size_t)p0 * FF;

    for (int i = tid; i < 16 * 64; i += 256) {
        int r = i >> 6, c = (i & 63) << 2;
        float4 v = *reinterpret_cast<const float4*>(xbase + r * FF + c);
        *reinterpret_cast<float4*>(&xs[r][c]) = v;
    }
    for (int i = tid; i < LL * FF; i += 256) pws[i >> 8][i & 255] = pw[i];
    __syncthreads();

    const int n = tid >> 4;
    const int l = tid & 15;
    ull a2 = 0ULL;
#pragma unroll 8
    for (int f2 = 0; f2 < FF / 2; f2++) {
        ull xv = *reinterpret_cast<const ull*>(&xs[n][f2 << 1]);
        ull wv = *reinterpret_cast<const ull*>(&pws[l][f2 << 1]);
        a2 = ffma2(xv, wv, a2);
    }
    float acc = hadd2(a2) + pb[l];

    g_z[(size_t)(p0 + n) * LL + l] = acc;
    red[n][l] = acc * acc;
    __syncthreads();
    if (l == 0) {
        float s = 0.f;
#pragma unroll
        for (int j = 0; j < LL; j++) s += red[n][j];
        g_sq[p0 + n] = s;
    }
}

// =====================================================================
// Kernel 1b: pi = sigmoid( relu(z @ w1^T + b1) @ w2^T + b2 )
// =====================================================================
__global__ void __launch_bounds__(256) k_pi(const float* __restrict__ w1,
                                            const float* __restrict__ b1,
                                            const float* __restrict__ w2,
                                            const float* __restrict__ b2) {
    __shared__ __align__(16) float zs[128][18];
    __shared__ __align__(16) float w1s[256][16];
    __shared__ float b1s[256];
    __shared__ float w2s[256];

    const int tid = threadIdx.x;
    const int p0 = blockIdx.x * 128;

    for (int i = tid; i < 128 * LL; i += 256) zs[i >> 4][i & 15] = g_z[(size_t)p0 * LL + i];
    for (int i = tid; i < FF * LL; i += 256) w1s[i >> 4][i & 15] = w1[i];
    b1s[tid] = b1[tid];
    w2s[tid] = w2[tid];
    __syncthreads();

    const int p = tid >> 1;
    const int h = tid & 1;
    ull zp[8];
#pragma unroll
    for (int l2 = 0; l2 < 8; l2++) zp[l2] = *reinterpret_cast<const ull*>(&zs[p][l2 << 1]);

    float accum = 0.f;
    const int f0 = h * 128;
#pragma unroll 4
    for (int fo = 0; fo < 128; fo++) {
        const int f = f0 + fo;
        ull d2 = 0ULL;
#pragma unroll
        for (int l2 = 0; l2 < 8; l2++) {
            ull wv = *reinterpret_cast<const ull*>(&w1s[f][l2 << 1]);
            d2 = ffma2(zp[l2], wv, d2);
        }
        float hv = hadd2(d2) + b1s[f];
        hv = fmaxf(hv, 0.f);
        accum = fmaf(hv, w2s[f], accum);
    }
    accum += __shfl_xor_sync(0xffffffffu, accum, 1);
    if (h == 0) {
        float t = accum + b2[0];
        g_pi[p0 + p] = 1.0f / (1.0f + __expf(-t));
    }
}

// =====================================================================
// Kernel 2: symmetric K pass. Tile pairs (ti<=tj) of 128x128.
// Each pair computed ONCE; tile + transpose written; q partials stored
// to unique (slot,row) cells. exp predicated on d2<16 (fp16 underflow).
// Grid: (NPAIRS, BB), 256 threads.
// =====================================================================
#define KT_PITCH 130
#define KK_ZN    0u
#define KK_ZM    9216u
#define KK_SQN   18432u
#define KK_SQM   18944u
#define KK_KT    19456u
#define KK_KTT   52736u
#define KK_RED   86016u
#define KK_SMEM  87040u

__global__ void __launch_bounds__(256, 2) k_K(void) {
    extern __shared__ __align__(16) unsigned char ks[];
    float (*zn)[18]  = reinterpret_cast<float(*)[18]>(ks + KK_ZN);
    float (*zm)[18]  = reinterpret_cast<float(*)[18]>(ks + KK_ZM);
    float* sqn = reinterpret_cast<float*>(ks + KK_SQN);
    float* sqm = reinterpret_cast<float*>(ks + KK_SQM);
    __half (*Kt)[KT_PITCH]  = reinterpret_cast<__half(*)[KT_PITCH]>(ks + KK_KT);
    __half (*KtT)[KT_PITCH] = reinterpret_cast<__half(*)[KT_PITCH]>(ks + KK_KTT);
    float (*red)[2] = reinterpret_cast<float(*)[2]>(ks + KK_RED);

    const int tid = threadIdx.x;
    const int b = blockIdx.y;
    int p = blockIdx.x, ti = 0;
    while (p >= NT - ti) { p -= NT - ti; ti++; }
    const int tj = ti + p;
    const bool diag = (ti == tj);

    const float* zb = g_z + (size_t)b * NN * LL;
    const float* sqb = g_sq + (size_t)b * NN;
    for (int i = tid; i < 128 * 16; i += 256) {
        zn[i >> 4][i & 15] = zb[(size_t)(ti * 128) * LL + i];
        zm[i >> 4][i & 15] = zb[(size_t)(tj * 128) * LL + i];
    }
    if (tid < 128) { sqn[tid] = sqb[ti * 128 + tid]; sqm[tid] = sqb[tj * 128 + tid]; }
    __syncthreads();

    const int n = tid & 127, mh = tid >> 7;
    ull znp[8];
#pragma unroll
    for (int l2 = 0; l2 < 8; l2++) znp[l2] = *reinterpret_cast<const ull*>(&zn[n][l2 << 1]);
    const float sqnr = sqn[n];

    float rsum = 0.f;
#pragma unroll 4
    for (int j = 0; j < 64; j++) {
        const int m = mh * 64 + j;
        ull d64 = 0ULL;
#pragma unroll
        for (int l2 = 0; l2 < 8; l2++)
            d64 = ffma2(znp[l2], *reinterpret_cast<const ull*>(&zm[m][l2 << 1]), d64);
        float dot = hadd2(d64);
        float d2 = fmaxf(sqnr + sqm[m] - 2.0f * dot, 0.f);
        float kv = 0.f;
        if (d2 < 16.0f) kv = __expf(-d2);   // kscale = 1/(4*eps) = 1
        rsum += kv;
        __half kh = __float2half_rn(kv);
        Kt[n][m] = kh;
        KtT[m][n] = kh;
    }
    red[n][mh] = rsum;
    __syncthreads();
    if (tid < 128)
        g_qpart[((size_t)b * NT + tj) * NN + ti * 128 + tid] = red[tid][0] + red[tid][1];

    // column sums (rowsum of transpose) — skip entirely for diag tiles
    float csum = 0.f;
    if (!diag) {
        const int m2 = tid & 127, nh2 = tid >> 7;
#pragma unroll 8
        for (int j = 0; j < 32; j++) {
            __half2 hv = *reinterpret_cast<const __half2*>(&KtT[m2][nh2 * 64 + 2 * j]);
            float2 fv = __half22float2(hv);
            csum += fv.x + fv.y;
        }
    }
    __syncthreads();
    red[tid & 127][tid >> 7] = csum;
    __syncthreads();
    if (!diag && tid < 128)
        g_qpart[((size_t)b * NT + ti) * NN + tj * 128 + tid] = red[tid][0] + red[tid][1];

    // writeout (coalesced word copies)
    uint32_t* gK1 = reinterpret_cast<uint32_t*>(
        g_K + ((size_t)(b * NN + ti * 128)) * NN + tj * 128);
    const uint32_t* ktw = reinterpret_cast<const uint32_t*>(Kt);   // pitch 65 words
    for (int i = tid; i < 128 * 64; i += 256)
        gK1[(size_t)(i >> 6) * (NN / 2) + (i & 63)] = ktw[(i >> 6) * 65 + (i & 63)];
    if (!diag) {
        uint32_t* gK2 = reinterpret_cast<uint32_t*>(
            g_K + ((size_t)(b * NN + tj * 128)) * NN + ti * 128);
        const uint32_t* ktt = reinterpret_cast<const uint32_t*>(KtT);
        for (int i = tid; i < 128 * 64; i += 256)
            gK2[(size_t)(i >> 6) * (NN / 2) + (i & 63)] = ktt[(i >> 6) * 65 + (i & 63)];
    }
}

// =====================================================================
// Kernel 3: q = sum of partials ; c = pi/q ; y[f][m] = c[m]*x[m][f] fp16.
// Grid: (MTILES, B), 256 threads.
// =====================================================================
__global__ void __launch_bounds__(256) k_y(const float* __restrict__ x) {
    __shared__ float cs[TK];
    __shared__ uint32_t yt[256][33];

    const int tid = threadIdx.x;
    const int mt = blockIdx.x, b = blockIdx.y;
    const float* xb = x + ((size_t)b * NN + mt * TK) * FF;

    if (tid < TK) {
        const int lm = mt * TK + tid;
        float q = 0.f;
#pragma unroll
        for (int s = 0; s < NT; s++) q += g_qpart[((size_t)b * NT + s) * NN + lm];
        float c = g_pi[b * NN + lm] / q;
        g_c[b * NN + lm] = c;
        cs[tid] = c;
    }
    __syncthreads();

    const int f = tid;
#pragma unroll 8
    for (int j = 0; j < 32; j++) {
        float y0 = cs[2 * j]     * __ldg(xb + (size_t)(2 * j) * FF + f);
        float y1 = cs[2 * j + 1] * __ldg(xb + (size_t)(2 * j + 1) * FF + f);
        __half2 hv = __floats2half2_rn(y0, y1);
        yt[f][j] = *reinterpret_cast<uint32_t*>(&hv);
    }
    __syncthreads();
    uint32_t* gY = reinterpret_cast<uint32_t*>(g_y + ((size_t)b * FF * NN + mt * TK));
    for (int i = tid; i < 256 * 32; i += 256)
        gY[(size_t)(i >> 5) * (NN / 2) + (i & 31)] = yt[i >> 5][i & 31];
}

// =====================================================================
// Kernel 4: HMMA GEMM with ldmatrix fragment loads.
// out-tile 64 x 256 per CTA; 8 warps (2m x 4n), warp 32x64, k-tile 64.
// =====================================================================
#define APITCH 72              // halves (144B rows; LDSM conflict-free)
#define ABYTES (64 * 144)
#define BBYTES (256 * 144)
#define BUFBYTES (ABYTES + BBYTES)
#define OFF_C  (2 * BUFBYTES)
#define OFF_RS (OFF_C + 512)
#define OFF_SC (OFF_RS + 1024)
#define SMEM_TOTAL (OFF_SC + 256)

__global__ void __launch_bounds__(256, 2)
k_main(const float* __restrict__ x, float* __restrict__ out,
       const float* __restrict__ dtp) {
    extern __shared__ __align__(16) unsigned char sm[];
    const unsigned smb = smem_u32(sm);

    const int tid = threadIdx.x;
    const int nb = blockIdx.x, b = blockIdx.y;
    const int wid = tid >> 5, lane = tid & 31;
    const int g = lane >> 2, q = lane & 3;
    const int wm = wid & 1, wn = wid >> 1;

    const __half* Kg = g_K + (size_t)(b * NN + nb * 64) * NN;
    const __half* Yg = g_y + (size_t)b * FF * NN;
    const float* cg = g_c + (size_t)b * NN;

    auto fill = [&](int t, int buf) {
        const unsigned base = smb + buf * BUFBYTES;
        const __half* aG = Kg + t * TK;
        const __half* bG = Yg + t * TK;
        for (int i = tid; i < 512; i += 256)
            cp_async16s(base + (i >> 3) * 144 + (i & 7) * 16,
                        aG + (size_t)(i >> 3) * NN + (i & 7) * 8);
        for (int i = tid; i < 2048; i += 256)
            cp_async16s(base + ABYTES + (i >> 3) * 144 + (i & 7) * 16,
                        bG + (size_t)(i >> 3) * NN + (i & 7) * 8);
        if (tid < 16)
            cp_async16s(smb + OFF_C + buf * 256 + tid * 16, cg + t * TK + tid * 4);
        cp_commit();
    };

    fill(0, 0);
    fill(1, 1);

    float acc[2][8][4];
#pragma unroll
    for (int mf = 0; mf < 2; mf++)
#pragma unroll
        for (int nf = 0; nf < 8; nf++)
#pragma unroll
            for (int k = 0; k < 4; k++) acc[mf][nf][k] = 0.f;
    float rs = 0.f;
    const int rn = tid & 63, qm = tid >> 6;

    // ldmatrix lane-address components (constant per thread)
    const int a_row = wm * 32 + (lane & 15);            // + mf*16
    const int a_kof = (lane >> 4) << 3;
    const int b_row = wn * 64 + (lane & 7) + ((lane >> 4) << 3);   // + np*16
    const int b_kof = ((lane >> 3) & 1) << 3;

    for (int t = 0; t < MTILES; t++) {
        const int buf = t & 1;
        if (t < MTILES - 1) cp_wait1(); else cp_wait0();
        __syncthreads();

        const unsigned KsA = smb + buf * BUFBYTES;
        const unsigned YsA = KsA + ABYTES;
        const __half* Ks = reinterpret_cast<const __half*>(sm + buf * BUFBYTES);

        // rowsum partial: thread (rn, qm) covers 16 m
        {
            const float* cP = reinterpret_cast<const float*>(sm + OFF_C + buf * 256);
#pragma unroll
            for (int j = 0; j < 8; j++) {
                __half2 hv = *reinterpret_cast<const __half2*>(Ks + rn * APITCH + qm * 16 + 2 * j);
                float2 fv = __half22float2(hv);
                rs = fmaf(fv.x, cP[qm * 16 + 2 * j], rs);
                rs = fmaf(fv.y, cP[qm * 16 + 2 * j + 1], rs);
            }
        }

#pragma unroll
        for (int ksI = 0; ksI < 4; ksI++) {
            const int k0 = ksI * 16;
            uint32_t af[2][4];
#pragma unroll
            for (int mf = 0; mf < 2; mf++)
                ldsm4(af[mf], KsA + ((a_row + mf * 16) * APITCH + k0 + a_kof) * 2);
            uint32_t bf[8][2];
#pragma unroll
            for (int np = 0; np < 4; np++) {
                uint32_t r4[4];
                ldsm4(r4, YsA + ((b_row + np * 16) * APITCH + k0 + b_kof) * 2);
                bf[np * 2][0] = r4[0]; bf[np * 2][1] = r4[1];
                bf[np * 2 + 1][0] = r4[2]; bf[np * 2 + 1][1] = r4[3];
            }
#pragma unroll
            for (int mf = 0; mf < 2; mf++)
#pragma unroll
                for (int nf = 0; nf < 8; nf++)
                    mma16816(acc[mf][nf], af[mf], bf[nf]);
        }
        __syncthreads();
        if (t + 2 < MTILES) fill(t + 2, buf);
    }

    // rowsum reduce -> rowscale
    reinterpret_cast<float*>(sm + OFF_RS)[rn * 4 + qm] = rs;
    __syncthreads();
    const float dtv = dtp[0];
    if (tid < 64) {
        const float* rp = reinterpret_cast<const float*>(sm + OFF_RS) + tid * 4;
        float row = rp[0] + rp[1] + rp[2] + rp[3] + 1e-5f;
        reinterpret_cast<float*>(sm + OFF_SC)[tid] = (dtv / EPSV) / row;
    }
    __syncthreads();

    // epilogue
    const float omdt = 1.0f - dtv;
    const float* scS = reinterpret_cast<const float*>(sm + OFF_SC);
#pragma unroll
    for (int mf = 0; mf < 2; mf++) {
        const int lr = wm * 32 + mf * 16 + g;
        const float sc1 = scS[lr], sc2 = scS[lr + 8];
        const size_t r1 = (size_t)(b * NN + nb * 64 + lr) * FF;
        const size_t r2 = r1 + (size_t)8 * FF;
#pragma unroll
        for (int nf = 0; nf < 8; nf++) {
            const int col = wn * 64 + nf * 8 + 2 * q;
            float2 x1 = *reinterpret_cast<const float2*>(x + r1 + col);
            float2 x2 = *reinterpret_cast<const float2*>(x + r2 + col);
            float2 o1, o2;
            o1.x = omdt * x1.x + sc1 * acc[mf][nf][0];
            o1.y = omdt * x1.y + sc1 * acc[mf][nf][1];
            o2.x = omdt * x2.x + sc2 * acc[mf][nf][2];
            o2.y = omdt * x2.y + sc2 * acc[mf][nf][3];
            *reinterpret_cast<float2*>(out + r1 + col) = o1;
            *reinterpret_cast<float2*>(out + r2 + col) = o2;
        }
    }
}

// =====================================================================
// launch
// =====================================================================
extern "C" void kernel_launch(void* const* d_in, const int* in_sizes, int n_in,
                              void* d_out, int out_size) {
    const float* x  = (const float*)d_in[0];
    const float* pw = (const float*)d_in[1];
    const float* pb = (const float*)d_in[2];
    const float* w1 = (const float*)d_in[3];
    const float* b1 = (const float*)d_in[4];
    const float* w2 = (const float*)d_in[5];
    const float* b2 = (const float*)d_in[6];
    const float* dt = (const float*)d_in[7];
    float* out = (float*)d_out;

    (void)in_sizes; (void)n_in; (void)out_size;

    const int npts = BB * NN;

    k_proj<<<npts / 16, 256>>>(x, pw, pb);
    k_pi<<<npts / 128, 256>>>(w1, b1, w2, b2);

    cudaFuncSetAttribute(k_K, cudaFuncAttributeMaxDynamicSharedMemorySize, (int)KK_SMEM);
    k_K<<<dim3(NPAIRS, BB), 256, KK_SMEM>>>();

    k_y<<<dim3(MTILES, BB), 256>>>(x);

    cudaFuncSetAttribute(k_main, cudaFuncAttributeMaxDynamicSharedMemorySize,
                         (int)SMEM_TOTAL);
    k_main<<<dim3(NN / 64, BB), 256, SMEM_TOTAL>>>(x, out, dt);
}

// round 6
// speedup vs baseline: 3.9956x; 1.0012x over previous
#include <cuda_runtime.h>
#include <cuda_fp16.h>
#include <cstdint>

// Problem constants (TMDLayer): B=8, N=2048, F=256, L=16, EPS=0.25
#define BB 8
#define NN 2048
#define FF 256
#define LL 16
#define EPSV 0.25f
#define MTILES 32      // m-tiles of 64 (k_y)
#define TK 64
#define NT 16          // k_K tiles of 128
#define NPAIRS 136     // NT*(NT+1)/2

typedef unsigned long long ull;

// ---------------- device scratch ----------------
__device__ float g_z[BB * NN * LL];
__device__ float g_sq[BB * NN];
__device__ float g_pi[BB * NN];
__device__ float g_c[BB * NN];
__device__ float g_qpart[(size_t)BB * NT * NN];
__device__ __align__(128) __half g_K[(size_t)BB * NN * NN];   // [b][n][m]
__device__ __align__(128) __half g_y[(size_t)BB * FF * NN];   // [b][f][m]

// ---------------- helpers ----------------
__device__ __forceinline__ unsigned smem_u32(const void* p) {
    unsigned a;
    asm("{ .reg .u64 t; cvta.to.shared.u64 t, %1; cvt.u32.u64 %0, t; }" : "=r"(a) : "l"(p));
    return a;
}
__device__ __forceinline__ void cp_async16s(unsigned dst, const void* src) {
    asm volatile("cp.async.cg.shared.global [%0], [%1], 16;\n" :: "r"(dst), "l"(src));
}
__device__ __forceinline__ void cp_commit() { asm volatile("cp.async.commit_group;\n"); }
__device__ __forceinline__ void cp_wait0() { asm volatile("cp.async.wait_group 0;\n"); }
__device__ __forceinline__ void cp_wait1() { asm volatile("cp.async.wait_group 1;\n"); }

__device__ __forceinline__ ull ffma2(ull a, ull b, ull c) {
    ull d;
    asm("fma.rn.f32x2 %0, %1, %2, %3;" : "=l"(d) : "l"(a), "l"(b), "l"(c));
    return d;
}
union F2U { ull u; float2 f; };
__device__ __forceinline__ float hadd2(ull v) { F2U t; t.u = v; return t.f.x + t.f.y; }

__device__ __forceinline__ void mma16816(float* d, const uint32_t* a, const uint32_t* b) {
    asm volatile(
        "mma.sync.aligned.m16n8k16.row.col.f32.f16.f16.f32 "
        "{%0,%1,%2,%3}, {%4,%5,%6,%7}, {%8,%9}, {%0,%1,%2,%3};"
        : "+f"(d[0]), "+f"(d[1]), "+f"(d[2]), "+f"(d[3])
        : "r"(a[0]), "r"(a[1]), "r"(a[2]), "r"(a[3]), "r"(b[0]), "r"(b[1]));
}
__device__ __forceinline__ void ldsm4(uint32_t* r, unsigned addr) {
    asm volatile("ldmatrix.sync.aligned.m8n8.x4.shared.b16 {%0,%1,%2,%3}, [%4];"
        : "=r"(r[0]), "=r"(r[1]), "=r"(r[2]), "=r"(r[3]) : "r"(addr));
}

// =====================================================================
// Kernel 1 (fused): z = x@pw^T + pb ; sq = |z|^2 ;
//                   pi = sigmoid( relu(z@w1^T + b1) @ w2^T + b2 )
// Block: 256 threads = 16 points x 16 lanes. Grid: B*N/16 = 1024.
// =====================================================================
__global__ void __launch_bounds__(256) k_zpi(const float* __restrict__ x,
                                             const float* __restrict__ pw,
                                             const float* __restrict__ pb,
                                             const float* __restrict__ w1,
                                             const float* __restrict__ b1,
                                             const float* __restrict__ w2,
                                             const float* __restrict__ b2) {
    __shared__ __align__(16) float xs[16][260];
    __shared__ __align__(16) float pws[16][258];
    __shared__ __align__(16) float zs[16][18];
    __shared__ float red[16][17];
    __shared__ __align__(16) float w1s[256][18];   // pitch 18: conflict-free + 8B aligned
    __shared__ float b1s[256];
    __shared__ float w2s[256];

    const int tid = threadIdx.x;
    const int p0 = blockIdx.x * 16;
    const float* xbase = x + (size_t)p0 * FF;

    for (int i = tid; i < 16 * 64; i += 256) {
        int r = i >> 6, c = (i & 63) << 2;
        float4 v = *reinterpret_cast<const float4*>(xbase + r * FF + c);
        *reinterpret_cast<float4*>(&xs[r][c]) = v;
    }
    for (int i = tid; i < LL * FF; i += 256) pws[i >> 8][i & 255] = pw[i];
    for (int i = tid; i < FF * LL; i += 256) w1s[i >> 4][i & 15] = w1[i];
    b1s[tid] = b1[tid];
    w2s[tid] = w2[tid];
    __syncthreads();

    const int n = tid >> 4;
    const int l = tid & 15;
    ull a2 = 0ULL;
#pragma unroll 8
    for (int f2 = 0; f2 < FF / 2; f2++) {
        ull xv = *reinterpret_cast<const ull*>(&xs[n][f2 << 1]);
        ull wv = *reinterpret_cast<const ull*>(&pws[l][f2 << 1]);
        a2 = ffma2(xv, wv, a2);
    }
    float acc = hadd2(a2) + pb[l];

    g_z[(size_t)(p0 + n) * LL + l] = acc;
    zs[n][l] = acc;
    red[n][l] = acc * acc;
    __syncthreads();
    if (l == 0) {
        float s = 0.f;
#pragma unroll
        for (int j = 0; j < LL; j++) s += red[n][j];
        g_sq[p0 + n] = s;
    }

    // --- pi: each thread covers f = l + 16*i (i=0..15) ---
    ull zp[8];
#pragma unroll
    for (int l2 = 0; l2 < 8; l2++) zp[l2] = *reinterpret_cast<const ull*>(&zs[n][l2 << 1]);

    float accum = 0.f;
#pragma unroll 4
    for (int i = 0; i < 16; i++) {
        const int f = l + 16 * i;
        ull d2 = 0ULL;
#pragma unroll
        for (int l2 = 0; l2 < 8; l2++) {
            ull wv = *reinterpret_cast<const ull*>(&w1s[f][l2 << 1]);
            d2 = ffma2(zp[l2], wv, d2);
        }
        float hv = hadd2(d2) + b1s[f];
        hv = fmaxf(hv, 0.f);
        accum = fmaf(hv, w2s[f], accum);
    }
#pragma unroll
    for (int o = 8; o > 0; o >>= 1) accum += __shfl_down_sync(0xffffffffu, accum, o, 16);
    if (l == 0) {
        float t = accum + b2[0];
        g_pi[p0 + n] = 1.0f / (1.0f + __expf(-t));
    }
}

// =====================================================================
// Kernel 2: symmetric K pass (tile pairs of 128x128), exp predicated.
// Grid: (NPAIRS, BB), 256 threads.
// =====================================================================
#define KT_PITCH 130
#define KK_ZN    0u
#define KK_ZM    9216u
#define KK_SQN   18432u
#define KK_SQM   18944u
#define KK_KT    19456u
#define KK_KTT   52736u
#define KK_RED   86016u
#define KK_SMEM  87040u

__global__ void __launch_bounds__(256, 2) k_K(void) {
    extern __shared__ __align__(16) unsigned char ks[];
    float (*zn)[18]  = reinterpret_cast<float(*)[18]>(ks + KK_ZN);
    float (*zm)[18]  = reinterpret_cast<float(*)[18]>(ks + KK_ZM);
    float* sqn = reinterpret_cast<float*>(ks + KK_SQN);
    float* sqm = reinterpret_cast<float*>(ks + KK_SQM);
    __half (*Kt)[KT_PITCH]  = reinterpret_cast<__half(*)[KT_PITCH]>(ks + KK_KT);
    __half (*KtT)[KT_PITCH] = reinterpret_cast<__half(*)[KT_PITCH]>(ks + KK_KTT);
    float (*red)[2] = reinterpret_cast<float(*)[2]>(ks + KK_RED);

    const int tid = threadIdx.x;
    const int b = blockIdx.y;
    int p = blockIdx.x, ti = 0;
    while (p >= NT - ti) { p -= NT - ti; ti++; }
    const int tj = ti + p;
    const bool diag = (ti == tj);

    const float* zb = g_z + (size_t)b * NN * LL;
    const float* sqb = g_sq + (size_t)b * NN;
    for (int i = tid; i < 128 * 16; i += 256) {
        zn[i >> 4][i & 15] = zb[(size_t)(ti * 128) * LL + i];
        zm[i >> 4][i & 15] = zb[(size_t)(tj * 128) * LL + i];
    }
    if (tid < 128) { sqn[tid] = sqb[ti * 128 + tid]; sqm[tid] = sqb[tj * 128 + tid]; }
    __syncthreads();

    const int n = tid & 127, mh = tid >> 7;
    ull znp[8];
#pragma unroll
    for (int l2 = 0; l2 < 8; l2++) znp[l2] = *reinterpret_cast<const ull*>(&zn[n][l2 << 1]);
    const float sqnr = sqn[n];

    float rsum = 0.f;
#pragma unroll 4
    for (int j = 0; j < 64; j++) {
        const int m = mh * 64 + j;
        ull d64 = 0ULL;
#pragma unroll
        for (int l2 = 0; l2 < 8; l2++)
            d64 = ffma2(znp[l2], *reinterpret_cast<const ull*>(&zm[m][l2 << 1]), d64);
        float dot = hadd2(d64);
        float d2 = fmaxf(sqnr + sqm[m] - 2.0f * dot, 0.f);
        float kv = 0.f;
        if (d2 < 16.0f) kv = __expf(-d2);   // kscale = 1/(4*eps) = 1
        rsum += kv;
        __half kh = __float2half_rn(kv);
        Kt[n][m] = kh;
        KtT[m][n] = kh;
    }
    red[n][mh] = rsum;
    __syncthreads();
    if (tid < 128)
        g_qpart[((size_t)b * NT + tj) * NN + ti * 128 + tid] = red[tid][0] + red[tid][1];

    float csum = 0.f;
    if (!diag) {
        const int m2 = tid & 127, nh2 = tid >> 7;
#pragma unroll 8
        for (int j = 0; j < 32; j++) {
            __half2 hv = *reinterpret_cast<const __half2*>(&KtT[m2][nh2 * 64 + 2 * j]);
            float2 fv = __half22float2(hv);
            csum += fv.x + fv.y;
        }
    }
    __syncthreads();
    red[tid & 127][tid >> 7] = csum;
    __syncthreads();
    if (!diag && tid < 128)
        g_qpart[((size_t)b * NT + ti) * NN + tj * 128 + tid] = red[tid][0] + red[tid][1];

    uint32_t* gK1 = reinterpret_cast<uint32_t*>(
        g_K + ((size_t)(b * NN + ti * 128)) * NN + tj * 128);
    const uint32_t* ktw = reinterpret_cast<const uint32_t*>(Kt);   // pitch 65 words
    for (int i = tid; i < 128 * 64; i += 256)
        gK1[(size_t)(i >> 6) * (NN / 2) + (i & 63)] = ktw[(i >> 6) * 65 + (i & 63)];
    if (!diag) {
        uint32_t* gK2 = reinterpret_cast<uint32_t*>(
            g_K + ((size_t)(b * NN + tj * 128)) * NN + ti * 128);
        const uint32_t* ktt = reinterpret_cast<const uint32_t*>(KtT);
        for (int i = tid; i < 128 * 64; i += 256)
            gK2[(size_t)(i >> 6) * (NN / 2) + (i & 63)] = ktt[(i >> 6) * 65 + (i & 63)];
    }
}

// =====================================================================
// Kernel 3: q = sum partials ; c = pi/q ; y[f][m] = c[m]*x[m][f] fp16.
// =====================================================================
__global__ void __launch_bounds__(256) k_y(const float* __restrict__ x) {
    __shared__ float cs[TK];
    __shared__ uint32_t yt[256][33];

    const int tid = threadIdx.x;
    const int mt = blockIdx.x, b = blockIdx.y;
    const float* xb = x + ((size_t)b * NN + mt * TK) * FF;

    if (tid < TK) {
        const int lm = mt * TK + tid;
        float q = 0.f;
#pragma unroll
        for (int s = 0; s < NT; s++) q += g_qpart[((size_t)b * NT + s) * NN + lm];
        float c = g_pi[b * NN + lm] / q;
        g_c[b * NN + lm] = c;
        cs[tid] = c;
    }
    __syncthreads();

    const int f = tid;
#pragma unroll 8
    for (int j = 0; j < 32; j++) {
        float y0 = cs[2 * j]     * __ldg(xb + (size_t)(2 * j) * FF + f);
        float y1 = cs[2 * j + 1] * __ldg(xb + (size_t)(2 * j + 1) * FF + f);
        __half2 hv = __floats2half2_rn(y0, y1);
        yt[f][j] = *reinterpret_cast<uint32_t*>(&hv);
    }
    __syncthreads();
    uint32_t* gY = reinterpret_cast<uint32_t*>(g_y + ((size_t)b * FF * NN + mt * TK));
    for (int i = tid; i < 256 * 32; i += 256)
        gY[(size_t)(i >> 5) * (NN / 2) + (i & 31)] = yt[i >> 5][i & 31];
}

// =====================================================================
// Kernel 4: HMMA GEMM, 3-stage cp.async pipeline, k-tile 32.
// out-tile 64 x 256 per CTA; 8 warps (2m x 4n); ONE sync per k-tile.
// =====================================================================
#define KAPITCH 40                    // halves (80B rows; LDSM conflict-free)
#define ABYTES3 (64 * 80)             // 5120
#define BBYTES3 (256 * 80)            // 20480
#define STAGE (ABYTES3 + BBYTES3)     // 25600
#define NSTAGE 3
#define KTILES 64                     // k = 32 each
#define OFF_C3  (NSTAGE * STAGE)      // 76800: 3 x 32 floats
#define OFF_RS3 (OFF_C3 + 384)        // 77184: 64 x 4 floats
#define OFF_SC3 (OFF_RS3 + 1024)      // 78208: 64 floats
#define SMEM3   (OFF_SC3 + 256)       // 78464

__global__ void __launch_bounds__(256, 2)
k_main(const float* __restrict__ x, float* __restrict__ out,
       const float* __restrict__ dtp) {
    extern __shared__ __align__(16) unsigned char sm[];
    const unsigned smb = smem_u32(sm);

    const int tid = threadIdx.x;
    const int nb = blockIdx.x, b = blockIdx.y;
    const int wid = tid >> 5, lane = tid & 31;
    const int g = lane >> 2, q = lane & 3;
    const int wm = wid & 1, wn = wid >> 1;

    const __half* Kg = g_K + (size_t)(b * NN + nb * 64) * NN;
    const __half* Yg = g_y + (size_t)b * FF * NN;
    const float* cg = g_c + (size_t)b * NN;

    auto fill = [&](int t, int st) {
        const unsigned aS = smb + st * STAGE;
        const unsigned bS = aS + ABYTES3;
        const __half* aG = Kg + t * 32;
        const __half* bG = Yg + t * 32;
        {
            const int i = tid;                                  // 256 chunks for A
            cp_async16s(aS + (i >> 2) * 80 + (i & 3) * 16,
                        aG + (size_t)(i >> 2) * NN + (i & 3) * 8);
        }
        for (int i = tid; i < 1024; i += 256)                    // 1024 chunks for B
            cp_async16s(bS + (i >> 2) * 80 + (i & 3) * 16,
                        bG + (size_t)(i >> 2) * NN + (i & 3) * 8);
        if (tid < 8)
            cp_async16s(smb + OFF_C3 + st * 128 + tid * 16, cg + t * 32 + tid * 4);
        cp_commit();
    };

    fill(0, 0);
    fill(1, 1);

    float acc[2][8][4];
#pragma unroll
    for (int mf = 0; mf < 2; mf++)
#pragma unroll
        for (int nf = 0; nf < 8; nf++)
#pragma unroll
            for (int k = 0; k < 4; k++) acc[mf][nf][k] = 0.f;
    float rs = 0.f;
    const int rn = tid & 63, qm = tid >> 6;

    const int a_row = wm * 32 + (lane & 15);
    const int a_kof = (lane >> 4) << 3;
    const int b_row = wn * 64 + (lane & 7) + ((lane >> 4) << 3);
    const int b_kof = ((lane >> 3) & 1) << 3;

    for (int t = 0; t < KTILES; t++) {
        const int st = t % NSTAGE;
        if (t < KTILES - 1) cp_wait1(); else cp_wait0();
        __syncthreads();
        if (t + 2 < KTILES) fill(t + 2, (t + 2) % NSTAGE);

        const unsigned KsA = smb + st * STAGE;
        const unsigned YsA = KsA + ABYTES3;
        const __half* Ks = reinterpret_cast<const __half*>(sm + st * STAGE);

        // rowsum partial: thread (rn, qm) covers 8 m of this 32-k tile
        {
            const float* cP = reinterpret_cast<const float*>(sm + OFF_C3 + st * 128);
#pragma unroll
            for (int j = 0; j < 4; j++) {
                __half2 hv = *reinterpret_cast<const __half2*>(Ks + rn * KAPITCH + qm * 8 + 2 * j);
                float2 fv = __half22float2(hv);
                rs = fmaf(fv.x, cP[qm * 8 + 2 * j], rs);
                rs = fmaf(fv.y, cP[qm * 8 + 2 * j + 1], rs);
            }
        }

#pragma unroll
        for (int ksI = 0; ksI < 2; ksI++) {
            const int k0 = ksI * 16;
            uint32_t af[2][4];
#pragma unroll
            for (int mf = 0; mf < 2; mf++)
                ldsm4(af[mf], KsA + ((a_row + mf * 16) * KAPITCH + k0 + a_kof) * 2);
            uint32_t bf[8][2];
#pragma unroll
            for (int np = 0; np < 4; np++) {
                uint32_t r4[4];
                ldsm4(r4, YsA + ((b_row + np * 16) * KAPITCH + k0 + b_kof) * 2);
                bf[np * 2][0] = r4[0]; bf[np * 2][1] = r4[1];
                bf[np * 2 + 1][0] = r4[2]; bf[np * 2 + 1][1] = r4[3];
            }
#pragma unroll
            for (int mf = 0; mf < 2; mf++)
#pragma unroll
                for (int nf = 0; nf < 8; nf++)
                    mma16816(acc[mf][nf], af[mf], bf[nf]);
        }
    }

    __syncthreads();
    reinterpret_cast<float*>(sm + OFF_RS3)[rn * 4 + qm] = rs;
    __syncthreads();
    const float dtv = dtp[0];
    if (tid < 64) {
        const float* rp = reinterpret_cast<const float*>(sm + OFF_RS3) + tid * 4;
        float row = rp[0] + rp[1] + rp[2] + rp[3] + 1e-5f;
        reinterpret_cast<float*>(sm + OFF_SC3)[tid] = (dtv / EPSV) / row;
    }
    __syncthreads();

    const float omdt = 1.0f - dtv;
    const float* scS = reinterpret_cast<const float*>(sm + OFF_SC3);
#pragma unroll
    for (int mf = 0; mf < 2; mf++) {
        const int lr = wm * 32 + mf * 16 + g;
        const float sc1 = scS[lr], sc2 = scS[lr + 8];
        const size_t r1 = (size_t)(b * NN + nb * 64 + lr) * FF;
        const size_t r2 = r1 + (size_t)8 * FF;
#pragma unroll
        for (int nf = 0; nf < 8; nf++) {
            const int col = wn * 64 + nf * 8 + 2 * q;
            float2 x1 = *reinterpret_cast<const float2*>(x + r1 + col);
            float2 x2 = *reinterpret_cast<const float2*>(x + r2 + col);
            float2 o1, o2;
            o1.x = omdt * x1.x + sc1 * acc[mf][nf][0];
            o1.y = omdt * x1.y + sc1 * acc[mf][nf][1];
            o2.x = omdt * x2.x + sc2 * acc[mf][nf][2];
            o2.y = omdt * x2.y + sc2 * acc[mf][nf][3];
            *reinterpret_cast<float2*>(out + r1 + col) = o1;
            *reinterpret_cast<float2*>(out + r2 + col) = o2;
        }
    }
}

// =====================================================================
// launch
// =====================================================================
extern "C" void kernel_launch(void* const* d_in, const int* in_sizes, int n_in,
                              void* d_out, int out_size) {
    const float* x  = (const float*)d_in[0];
    const float* pw = (const float*)d_in[1];
    const float* pb = (const float*)d_in[2];
    const float* w1 = (const float*)d_in[3];
    const float* b1 = (const float*)d_in[4];
    const float* w2 = (const float*)d_in[5];
    const float* b2 = (const float*)d_in[6];
    const float* dt = (const float*)d_in[7];
    float* out = (float*)d_out;

    (void)in_sizes; (void)n_in; (void)out_size;

    const int npts = BB * NN;

    k_zpi<<<npts / 16, 256>>>(x, pw, pb, w1, b1, w2, b2);

    cudaFuncSetAttribute(k_K, cudaFuncAttributeMaxDynamicSharedMemorySize, (int)KK_SMEM);
    k_K<<<dim3(NPAIRS, BB), 256, KK_SMEM>>>();

    k_y<<<dim3(MTILES, BB), 256>>>(x);

    cudaFuncSetAttribute(k_main, cudaFuncAttributeMaxDynamicSharedMemorySize, (int)SMEM3);
    k_main<<<dim3(NN / 64, BB), 256, SMEM3>>>(x, out, dt);
}

// round 7
// speedup vs baseline: 4.5089x; 1.1285x over previous
#include <cuda_runtime.h>
#include <cuda_fp16.h>
#include <cstdint>

// Problem constants (TMDLayer): B=8, N=2048, F=256, L=16, EPS=0.25
#define BB 8
#define NN 2048
#define FF 256
#define LL 16
#define EPSV 0.25f
#define MTILES 32      // m-tiles of 64 (k_y)
#define TK 64
#define NT 16          // k_K tiles of 128
#define NPAIRS 136     // NT*(NT+1)/2

typedef unsigned long long ull;

// ---------------- device scratch ----------------
__device__ __half g_zh[BB * NN * LL];          // fp16 z (single rounding point)
__device__ float g_sqh[BB * NN];               // |z_h|^2 from rounded values
__device__ float g_pi[BB * NN];
__device__ float g_c[BB * NN];
__device__ float g_qpart[(size_t)BB * NT * NN];
__device__ __align__(128) __half g_K[(size_t)BB * NN * NN];   // [b][n][m]
__device__ __align__(128) __half g_y[(size_t)BB * FF * NN];   // [b][f][m]

// ---------------- helpers ----------------
__device__ __forceinline__ unsigned smem_u32(const void* p) {
    unsigned a;
    asm("{ .reg .u64 t; cvta.to.shared.u64 t, %1; cvt.u32.u64 %0, t; }" : "=r"(a) : "l"(p));
    return a;
}
__device__ __forceinline__ void cp_async16s(unsigned dst, const void* src) {
    asm volatile("cp.async.cg.shared.global [%0], [%1], 16;\n" :: "r"(dst), "l"(src));
}
__device__ __forceinline__ void cp_commit() { asm volatile("cp.async.commit_group;\n"); }
__device__ __forceinline__ void cp_wait0() { asm volatile("cp.async.wait_group 0;\n"); }
__device__ __forceinline__ void cp_wait1() { asm volatile("cp.async.wait_group 1;\n"); }

__device__ __forceinline__ ull ffma2(ull a, ull b, ull c) {
    ull d;
    asm("fma.rn.f32x2 %0, %1, %2, %3;" : "=l"(d) : "l"(a), "l"(b), "l"(c));
    return d;
}
union F2U { ull u; float2 f; };
__device__ __forceinline__ float hadd2(ull v) { F2U t; t.u = v; return t.f.x + t.f.y; }

__device__ __forceinline__ void mma16816(float* d, const uint32_t* a, const uint32_t* b) {
    asm volatile(
        "mma.sync.aligned.m16n8k16.row.col.f32.f16.f16.f32 "
        "{%0,%1,%2,%3}, {%4,%5,%6,%7}, {%8,%9}, {%0,%1,%2,%3};"
        : "+f"(d[0]), "+f"(d[1]), "+f"(d[2]), "+f"(d[3])
        : "r"(a[0]), "r"(a[1]), "r"(a[2]), "r"(a[3]), "r"(b[0]), "r"(b[1]));
}
__device__ __forceinline__ void ldsm4(uint32_t* r, unsigned addr) {
    asm volatile("ldmatrix.sync.aligned.m8n8.x4.shared.b16 {%0,%1,%2,%3}, [%4];"
        : "=r"(r[0]), "=r"(r[1]), "=r"(r[2]), "=r"(r[3]) : "r"(addr));
}

// =====================================================================
// Kernel 1 (fused): z = x@pw^T + pb ; zh = fp16(z) ; sqh = |zh|^2 ;
//                   pi = sigmoid( relu(z@w1^T + b1) @ w2^T + b2 )
// Block: 256 threads = 16 points x 16 lanes. Grid: B*N/16 = 1024.
// =====================================================================
__global__ void __launch_bounds__(256) k_zpi(const float* __restrict__ x,
                                             const float* __restrict__ pw,
                                             const float* __restrict__ pb,
                                             const float* __restrict__ w1,
                                             const float* __restrict__ b1,
                                             const float* __restrict__ w2,
                                             const float* __restrict__ b2) {
    __shared__ __align__(16) float xs[16][260];
    __shared__ __align__(16) float pws[16][258];
    __shared__ __align__(16) float zs[16][18];
    __shared__ float red[16][17];
    __shared__ __align__(16) float w1s[256][18];
    __shared__ float b1s[256];
    __shared__ float w2s[256];

    const int tid = threadIdx.x;
    const int p0 = blockIdx.x * 16;
    const float* xbase = x + (size_t)p0 * FF;

    for (int i = tid; i < 16 * 64; i += 256) {
        int r = i >> 6, c = (i & 63) << 2;
        float4 v = *reinterpret_cast<const float4*>(xbase + r * FF + c);
        *reinterpret_cast<float4*>(&xs[r][c]) = v;
    }
    for (int i = tid; i < LL * FF; i += 256) pws[i >> 8][i & 255] = pw[i];
    for (int i = tid; i < FF * LL; i += 256) w1s[i >> 4][i & 15] = w1[i];
    b1s[tid] = b1[tid];
    w2s[tid] = w2[tid];
    __syncthreads();

    const int n = tid >> 4;
    const int l = tid & 15;
    ull a2 = 0ULL;
#pragma unroll 8
    for (int f2 = 0; f2 < FF / 2; f2++) {
        ull xv = *reinterpret_cast<const ull*>(&xs[n][f2 << 1]);
        ull wv = *reinterpret_cast<const ull*>(&pws[l][f2 << 1]);
        a2 = ffma2(xv, wv, a2);
    }
    float acc = hadd2(a2) + pb[l];

    __half zh = __float2half_rn(acc);
    g_zh[(size_t)(p0 + n) * LL + l] = zh;
    float az = __half2float(zh);
    zs[n][l] = acc;             // fp32 for pi
    red[n][l] = az * az;        // sqh from rounded values (diag consistency)
    __syncthreads();
    if (l == 0) {
        float s = 0.f;
#pragma unroll
        for (int j = 0; j < LL; j++) s += red[n][j];
        g_sqh[p0 + n] = s;
    }

    // --- pi: each thread covers f = l + 16*i ---
    ull zp[8];
#pragma unroll
    for (int l2 = 0; l2 < 8; l2++) zp[l2] = *reinterpret_cast<const ull*>(&zs[n][l2 << 1]);

    float accum = 0.f;
#pragma unroll 4
    for (int i = 0; i < 16; i++) {
        const int f = l + 16 * i;
        ull d2 = 0ULL;
#pragma unroll
        for (int l2 = 0; l2 < 8; l2++) {
            ull wv = *reinterpret_cast<const ull*>(&w1s[f][l2 << 1]);
            d2 = ffma2(zp[l2], wv, d2);
        }
        float hv = hadd2(d2) + b1s[f];
        hv = fmaxf(hv, 0.f);
        accum = fmaf(hv, w2s[f], accum);
    }
#pragma unroll
    for (int o = 8; o > 0; o >>= 1) accum += __shfl_down_sync(0xffffffffu, accum, o, 16);
    if (l == 0) {
        float t = accum + b2[0];
        g_pi[p0 + n] = 1.0f / (1.0f + __expf(-t));
    }
}

// =====================================================================
// Kernel 2: symmetric K pass via HMMA Gram. Tile pairs (ti<=tj) 128x128.
// G = Zn @ Zm^T (fp16 in, fp32 acc); d2 = sqh_n + sqh_m - 2G;
// kv = exp(-d2) branchless; row/col sums from fragments via shfl.
// Grid: (NPAIRS, BB), 256 threads (8 warps x 16 rows).
// =====================================================================
#define GPW 12        // z smem pitch in words (24 halves)
#define KPW 68        // Kt pitch in words (136 halves)
#define KTPH 136      // KtT pitch in halves
#define O_ZN  0u
#define O_ZM  6144u
#define O_SQN 12288u
#define O_SQM 12800u
#define O_KT  13312u
#define O_KTT 48128u
#define O_RS  82944u
#define O_CS  83456u          // 8 x 132 floats
#define KK_SMEM 87680u

__global__ void __launch_bounds__(256, 2) k_K(void) {
    extern __shared__ __align__(16) unsigned char ks[];
    uint32_t* znW = reinterpret_cast<uint32_t*>(ks + O_ZN);
    uint32_t* zmW = reinterpret_cast<uint32_t*>(ks + O_ZM);
    float* sqnS = reinterpret_cast<float*>(ks + O_SQN);
    float* sqmS = reinterpret_cast<float*>(ks + O_SQM);
    uint32_t* ktW = reinterpret_cast<uint32_t*>(ks + O_KT);
    __half* ktT = reinterpret_cast<__half*>(ks + O_KTT);
    float* rsS = reinterpret_cast<float*>(ks + O_RS);
    float (*csS)[132] = reinterpret_cast<float(*)[132]>(ks + O_CS);

    const int tid = threadIdx.x;
    const int b = blockIdx.y;
    int p = blockIdx.x, ti = 0;
    while (p >= NT - ti) { p -= NT - ti; ti++; }
    const int tj = ti + p;
    const bool diag = (ti == tj);

    // load z tiles (fp16) + sq
    {
        const uint32_t* gn = reinterpret_cast<const uint32_t*>(
            g_zh + ((size_t)b * NN + ti * 128) * LL);
        const uint32_t* gm = reinterpret_cast<const uint32_t*>(
            g_zh + ((size_t)b * NN + tj * 128) * LL);
        for (int i = tid; i < 1024; i += 256) {
            znW[(i >> 3) * GPW + (i & 7)] = gn[i];
            zmW[(i >> 3) * GPW + (i & 7)] = gm[i];
        }
        const float* sqb = g_sqh + (size_t)b * NN;
        if (tid < 128) { sqnS[tid] = sqb[ti * 128 + tid]; sqmS[tid] = sqb[tj * 128 + tid]; }
    }
    __syncthreads();

    const int w = tid >> 5, lane = tid & 31;
    const int g = lane >> 2, q = lane & 3;
    const int r0 = w * 16 + g, r1 = r0 + 8;

    // A fragments (rows r0/r1, k=16)
    uint32_t af[4];
    af[0] = znW[r0 * GPW + q];
    af[1] = znW[r1 * GPW + q];
    af[2] = znW[r0 * GPW + q + 4];
    af[3] = znW[r1 * GPW + q + 4];

    float acc[16][4];
#pragma unroll
    for (int cf = 0; cf < 16; cf++) {
        acc[cf][0] = acc[cf][1] = acc[cf][2] = acc[cf][3] = 0.f;
        uint32_t bf[2];
        bf[0] = zmW[(cf * 8 + g) * GPW + q];
        bf[1] = zmW[(cf * 8 + g) * GPW + q + 4];
        mma16816(acc[cf], af, bf);
    }

    // elementwise: d2 -> exp -> stores + row/col partial sums
    const float sqr0 = sqnS[r0], sqr1 = sqnS[r1];
    float rs0 = 0.f, rs1 = 0.f;
#pragma unroll
    for (int cf = 0; cf < 16; cf++) {
        const int c0 = cf * 8 + 2 * q;
        float2 sqc = *reinterpret_cast<const float2*>(&sqmS[c0]);
        float d00 = fmaxf(fmaf(-2.f, acc[cf][0], sqr0 + sqc.x), 0.f);
        float d01 = fmaxf(fmaf(-2.f, acc[cf][1], sqr0 + sqc.y), 0.f);
        float d10 = fmaxf(fmaf(-2.f, acc[cf][2], sqr1 + sqc.x), 0.f);
        float d11 = fmaxf(fmaf(-2.f, acc[cf][3], sqr1 + sqc.y), 0.f);
        float k00 = __expf(-d00), k01 = __expf(-d01);
        float k10 = __expf(-d10), k11 = __expf(-d11);
        rs0 += k00 + k01;
        rs1 += k10 + k11;

        __half2 h0 = __floats2half2_rn(k00, k01);
        __half2 h1 = __floats2half2_rn(k10, k11);
        ktW[r0 * KPW + (c0 >> 1)] = *reinterpret_cast<uint32_t*>(&h0);
        ktW[r1 * KPW + (c0 >> 1)] = *reinterpret_cast<uint32_t*>(&h1);

        if (!diag) {
            ktT[c0 * KTPH + r0] = __low2half(h0);
            ktT[c0 * KTPH + r1] = __low2half(h1);
            ktT[(c0 + 1) * KTPH + r0] = __high2half(h0);
            ktT[(c0 + 1) * KTPH + r1] = __high2half(h1);
            float cs0 = k00 + k10, cs1 = k01 + k11;
#pragma unroll
            for (int o = 4; o <= 16; o <<= 1) {
                cs0 += __shfl_xor_sync(0xffffffffu, cs0, o);
                cs1 += __shfl_xor_sync(0xffffffffu, cs1, o);
            }
            if (g == 0) { csS[w][c0] = cs0; csS[w][c0 + 1] = cs1; }
        }
    }
    // row sums: reduce over q (lanes g*4+q)
    rs0 += __shfl_xor_sync(0xffffffffu, rs0, 1);
    rs0 += __shfl_xor_sync(0xffffffffu, rs0, 2);
    rs1 += __shfl_xor_sync(0xffffffffu, rs1, 1);
    rs1 += __shfl_xor_sync(0xffffffffu, rs1, 2);
    if (q == 0) { rsS[r0] = rs0; rsS[r1] = rs1; }
    __syncthreads();

    if (tid < 128)
        g_qpart[((size_t)b * NT + tj) * NN + ti * 128 + tid] = rsS[tid];
    if (!diag && tid < 128) {
        float s = 0.f;
#pragma unroll
        for (int ww = 0; ww < 8; ww++) s += csS[ww][tid];
        g_qpart[((size_t)b * NT + ti) * NN + tj * 128 + tid] = s;
    }

    // writeout (coalesced word copies)
    uint32_t* gK1 = reinterpret_cast<uint32_t*>(
        g_K + ((size_t)(b * NN + ti * 128)) * NN + tj * 128);
    for (int i = tid; i < 128 * 64; i += 256)
        gK1[(size_t)(i >> 6) * (NN / 2) + (i & 63)] = ktW[(i >> 6) * KPW + (i & 63)];
    if (!diag) {
        uint32_t* gK2 = reinterpret_cast<uint32_t*>(
            g_K + ((size_t)(b * NN + tj * 128)) * NN + ti * 128);
        const uint32_t* ktTW = reinterpret_cast<const uint32_t*>(ktT);
        for (int i = tid; i < 128 * 64; i += 256)
            gK2[(size_t)(i >> 6) * (NN / 2) + (i & 63)] = ktTW[(i >> 6) * KPW + (i & 63)];
    }
}

// =====================================================================
// Kernel 3: q = sum partials ; c = pi/q ; y[f][m] = c[m]*x[m][f] fp16.
// =====================================================================
__global__ void __launch_bounds__(256) k_y(const float* __restrict__ x) {
    __shared__ float cs[TK];
    __shared__ uint32_t yt[256][33];

    const int tid = threadIdx.x;
    const int mt = blockIdx.x, b = blockIdx.y;
    const float* xb = x + ((size_t)b * NN + mt * TK) * FF;

    if (tid < TK) {
        const int lm = mt * TK + tid;
        float q = 0.f;
#pragma unroll
        for (int s = 0; s < NT; s++) q += g_qpart[((size_t)b * NT + s) * NN + lm];
        float c = g_pi[b * NN + lm] / q;
        g_c[b * NN + lm] = c;
        cs[tid] = c;
    }
    __syncthreads();

    const int f = tid;
#pragma unroll 8
    for (int j = 0; j < 32; j++) {
        float y0 = cs[2 * j]     * __ldg(xb + (size_t)(2 * j) * FF + f);
        float y1 = cs[2 * j + 1] * __ldg(xb + (size_t)(2 * j + 1) * FF + f);
        __half2 hv = __floats2half2_rn(y0, y1);
        yt[f][j] = *reinterpret_cast<uint32_t*>(&hv);
    }
    __syncthreads();
    uint32_t* gY = reinterpret_cast<uint32_t*>(g_y + ((size_t)b * FF * NN + mt * TK));
    for (int i = tid; i < 256 * 32; i += 256)
        gY[(size_t)(i >> 5) * (NN / 2) + (i & 31)] = yt[i >> 5][i & 31];
}

// =====================================================================
// Kernel 4: HMMA GEMM, 3-stage cp.async pipeline, k-tile 32.
// out-tile 64 x 256 per CTA; 8 warps (2m x 4n); one sync per k-tile.
// =====================================================================
#define KAPITCH 40
#define ABYTES3 (64 * 80)
#define BBYTES3 (256 * 80)
#define STAGE (ABYTES3 + BBYTES3)
#define NSTAGE 3
#define KTILES 64
#define OFF_C3  (NSTAGE * STAGE)
#define OFF_RS3 (OFF_C3 + 384)
#define OFF_SC3 (OFF_RS3 + 1024)
#define SMEM3   (OFF_SC3 + 256)

__global__ void __launch_bounds__(256, 2)
k_main(const float* __restrict__ x, float* __restrict__ out,
       const float* __restrict__ dtp) {
    extern __shared__ __align__(16) unsigned char sm[];
    const unsigned smb = smem_u32(sm);

    const int tid = threadIdx.x;
    const int nb = blockIdx.x, b = blockIdx.y;
    const int wid = tid >> 5, lane = tid & 31;
    const int g = lane >> 2, q = lane & 3;
    const int wm = wid & 1, wn = wid >> 1;

    const __half* Kg = g_K + (size_t)(b * NN + nb * 64) * NN;
    const __half* Yg = g_y + (size_t)b * FF * NN;
    const float* cg = g_c + (size_t)b * NN;

    auto fill = [&](int t, int st) {
        const unsigned aS = smb + st * STAGE;
        const unsigned bS = aS + ABYTES3;
        const __half* aG = Kg + t * 32;
        const __half* bG = Yg + t * 32;
        {
            const int i = tid;
            cp_async16s(aS + (i >> 2) * 80 + (i & 3) * 16,
                        aG + (size_t)(i >> 2) * NN + (i & 3) * 8);
        }
        for (int i = tid; i < 1024; i += 256)
            cp_async16s(bS + (i >> 2) * 80 + (i & 3) * 16,
                        bG + (size_t)(i >> 2) * NN + (i & 3) * 8);
        if (tid < 8)
            cp_async16s(smb + OFF_C3 + st * 128 + tid * 16, cg + t * 32 + tid * 4);
        cp_commit();
    };

    fill(0, 0);
    fill(1, 1);

    float acc[2][8][4];
#pragma unroll
    for (int mf = 0; mf < 2; mf++)
#pragma unroll
        for (int nf = 0; nf < 8; nf++)
#pragma unroll
            for (int k = 0; k < 4; k++) acc[mf][nf][k] = 0.f;
    float rs = 0.f;
    const int rn = tid & 63, qm = tid >> 6;

    const int a_row = wm * 32 + (lane & 15);
    const int a_kof = (lane >> 4) << 3;
    const int b_row = wn * 64 + (lane & 7) + ((lane >> 4) << 3);
    const int b_kof = ((lane >> 3) & 1) << 3;

    for (int t = 0; t < KTILES; t++) {
        const int st = t % NSTAGE;
        if (t < KTILES - 1) cp_wait1(); else cp_wait0();
        __syncthreads();
        if (t + 2 < KTILES) fill(t + 2, (t + 2) % NSTAGE);

        const unsigned KsA = smb + st * STAGE;
        const unsigned YsA = KsA + ABYTES3;
        const __half* Ks = reinterpret_cast<const __half*>(sm + st * STAGE);

        {
            const float* cP = reinterpret_cast<const float*>(sm + OFF_C3 + st * 128);
#pragma unroll
            for (int j = 0; j < 4; j++) {
                __half2 hv = *reinterpret_cast<const __half2*>(Ks + rn * KAPITCH + qm * 8 + 2 * j);
                float2 fv = __half22float2(hv);
                rs = fmaf(fv.x, cP[qm * 8 + 2 * j], rs);
                rs = fmaf(fv.y, cP[qm * 8 + 2 * j + 1], rs);
            }
        }

#pragma unroll
        for (int ksI = 0; ksI < 2; ksI++) {
            const int k0 = ksI * 16;
            uint32_t af[2][4];
#pragma unroll
            for (int mf = 0; mf < 2; mf++)
                ldsm4(af[mf], KsA + ((a_row + mf * 16) * KAPITCH + k0 + a_kof) * 2);
            uint32_t bf[8][2];
#pragma unroll
            for (int np = 0; np < 4; np++) {
                uint32_t r4[4];
                ldsm4(r4, YsA + ((b_row + np * 16) * KAPITCH + k0 + b_kof) * 2);
                bf[np * 2][0] = r4[0]; bf[np * 2][1] = r4[1];
                bf[np * 2 + 1][0] = r4[2]; bf[np * 2 + 1][1] = r4[3];
            }
#pragma unroll
            for (int mf = 0; mf < 2; mf++)
#pragma unroll
                for (int nf = 0; nf < 8; nf++)
                    mma16816(acc[mf][nf], af[mf], bf[nf]);
        }
    }

    __syncthreads();
    reinterpret_cast<float*>(sm + OFF_RS3)[rn * 4 + qm] = rs;
    __syncthreads();
    const float dtv = dtp[0];
    if (tid < 64) {
        const float* rp = reinterpret_cast<const float*>(sm + OFF_RS3) + tid * 4;
        float row = rp[0] + rp[1] + rp[2] + rp[3] + 1e-5f;
        reinterpret_cast<float*>(sm + OFF_SC3)[tid] = (dtv / EPSV) / row;
    }
    __syncthreads();

    const float omdt = 1.0f - dtv;
    const float* scS = reinterpret_cast<const float*>(sm + OFF_SC3);
#pragma unroll
    for (int mf = 0; mf < 2; mf++) {
        const int lr = wm * 32 + mf * 16 + g;
        const float sc1 = scS[lr], sc2 = scS[lr + 8];
        const size_t r1 = (size_t)(b * NN + nb * 64 + lr) * FF;
        const size_t r2 = r1 + (size_t)8 * FF;
#pragma unroll
        for (int nf = 0; nf < 8; nf++) {
            const int col = wn * 64 + nf * 8 + 2 * q;
            float2 x1 = *reinterpret_cast<const float2*>(x + r1 + col);
            float2 x2 = *reinterpret_cast<const float2*>(x + r2 + col);
            float2 o1, o2;
            o1.x = omdt * x1.x + sc1 * acc[mf][nf][0];
            o1.y = omdt * x1.y + sc1 * acc[mf][nf][1];
            o2.x = omdt * x2.x + sc2 * acc[mf][nf][2];
            o2.y = omdt * x2.y + sc2 * acc[mf][nf][3];
            *reinterpret_cast<float2*>(out + r1 + col) = o1;
            *reinterpret_cast<float2*>(out + r2 + col) = o2;
        }
    }
}

// =====================================================================
// launch
// =====================================================================
extern "C" void kernel_launch(void* const* d_in, const int* in_sizes, int n_in,
                              void* d_out, int out_size) {
    const float* x  = (const float*)d_in[0];
    const float* pw = (const float*)d_in[1];
    const float* pb = (const float*)d_in[2];
    const float* w1 = (const float*)d_in[3];
    const float* b1 = (const float*)d_in[4];
    const float* w2 = (const float*)d_in[5];
    const float* b2 = (const float*)d_in[6];
    const float* dt = (const float*)d_in[7];
    float* out = (float*)d_out;

    (void)in_sizes; (void)n_in; (void)out_size;

    const int npts = BB * NN;

    k_zpi<<<npts / 16, 256>>>(x, pw, pb, w1, b1, w2, b2);

    cudaFuncSetAttribute(k_K, cudaFuncAttributeMaxDynamicSharedMemorySize, (int)KK_SMEM);
    k_K<<<dim3(NPAIRS, BB), 256, KK_SMEM>>>();

    k_y<<<dim3(MTILES, BB), 256>>>(x);

    cudaFuncSetAttribute(k_main, cudaFuncAttributeMaxDynamicSharedMemorySize, (int)SMEM3);
    k_main<<<dim3(NN / 64, BB), 256, SMEM3>>>(x, out, dt);
}

// round 8
// speedup vs baseline: 4.5574x; 1.0107x over previous
#include <cuda_runtime.h>
#include <cuda_fp16.h>
#include <cstdint>

// Problem constants (TMDLayer): B=8, N=2048, F=256, L=16, EPS=0.25
#define BB 8
#define NN 2048
#define FF 256
#define LL 16
#define EPSV 0.25f
#define MTILES 32      // m-tiles of 64 (k_y)
#define TK 64
#define NT 16          // k_K tiles of 128
#define NPAIRS 136     // NT*(NT+1)/2
#define NL2E 1.4426950408889634f      // log2(e)

typedef unsigned long long ull;

// ---------------- device scratch ----------------
__device__ __half g_zh[BB * NN * LL];          // fp16 z (single rounding point)
__device__ float g_sqh[BB * NN];               // |z_h|^2 from rounded values
__device__ float g_pi[BB * NN];
__device__ float g_c[BB * NN];
__device__ float g_qpart[(size_t)BB * NT * NN];
__device__ __align__(128) __half g_K[(size_t)BB * NN * NN];   // [b][n][m]
__device__ __align__(128) __half g_y[(size_t)BB * FF * NN];   // [b][f][m]

// ---------------- helpers ----------------
__device__ __forceinline__ unsigned smem_u32(const void* p) {
    unsigned a;
    asm("{ .reg .u64 t; cvta.to.shared.u64 t, %1; cvt.u32.u64 %0, t; }" : "=r"(a) : "l"(p));
    return a;
}
__device__ __forceinline__ void cp_async16s(unsigned dst, const void* src) {
    asm volatile("cp.async.cg.shared.global [%0], [%1], 16;\n" :: "r"(dst), "l"(src));
}
__device__ __forceinline__ void cp_commit() { asm volatile("cp.async.commit_group;\n"); }
__device__ __forceinline__ void cp_wait0() { asm volatile("cp.async.wait_group 0;\n"); }
__device__ __forceinline__ void cp_wait1() { asm volatile("cp.async.wait_group 1;\n"); }
__device__ __forceinline__ void cp_wait2() { asm volatile("cp.async.wait_group 2;\n"); }

__device__ __forceinline__ ull ffma2(ull a, ull b, ull c) {
    ull d;
    asm("fma.rn.f32x2 %0, %1, %2, %3;" : "=l"(d) : "l"(a), "l"(b), "l"(c));
    return d;
}
union F2U { ull u; float2 f; };
__device__ __forceinline__ float hadd2(ull v) { F2U t; t.u = v; return t.f.x + t.f.y; }

__device__ __forceinline__ void mma16816(float* d, const uint32_t* a, const uint32_t* b) {
    asm volatile(
        "mma.sync.aligned.m16n8k16.row.col.f32.f16.f16.f32 "
        "{%0,%1,%2,%3}, {%4,%5,%6,%7}, {%8,%9}, {%0,%1,%2,%3};"
        : "+f"(d[0]), "+f"(d[1]), "+f"(d[2]), "+f"(d[3])
        : "r"(a[0]), "r"(a[1]), "r"(a[2]), "r"(a[3]), "r"(b[0]), "r"(b[1]));
}
__device__ __forceinline__ void ldsm4(uint32_t* r, unsigned addr) {
    asm volatile("ldmatrix.sync.aligned.m8n8.x4.shared.b16 {%0,%1,%2,%3}, [%4];"
        : "=r"(r[0]), "=r"(r[1]), "=r"(r[2]), "=r"(r[3]) : "r"(addr));
}
__device__ __forceinline__ uint32_t ex2_f16x2(uint32_t a) {
    uint32_t d;
    asm("ex2.approx.f16x2 %0, %1;" : "=r"(d) : "r"(a));
    return d;
}
__device__ __forceinline__ uint32_t movmat_t(uint32_t a) {
    uint32_t d;
    asm("movmatrix.sync.aligned.m8n8.trans.b16 %0, %1;" : "=r"(d) : "r"(a));
    return d;
}

// =====================================================================
// Kernel 1 (fused): z = x@pw^T + pb ; zh = fp16(z) ; sqh = |zh|^2 ;
//                   pi = sigmoid( relu(z@w1^T + b1) @ w2^T + b2 )
// =====================================================================
__global__ void __launch_bounds__(256) k_zpi(const float* __restrict__ x,
                                             const float* __restrict__ pw,
                                             const float* __restrict__ pb,
                                             const float* __restrict__ w1,
                                             const float* __restrict__ b1,
                                             const float* __restrict__ w2,
                                             const float* __restrict__ b2) {
    __shared__ __align__(16) float xs[16][260];
    __shared__ __align__(16) float pws[16][258];
    __shared__ __align__(16) float zs[16][18];
    __shared__ float red[16][17];
    __shared__ __align__(16) float w1s[256][18];
    __shared__ float b1s[256];
    __shared__ float w2s[256];

    const int tid = threadIdx.x;
    const int p0 = blockIdx.x * 16;
    const float* xbase = x + (size_t)p0 * FF;

    for (int i = tid; i < 16 * 64; i += 256) {
        int r = i >> 6, c = (i & 63) << 2;
        float4 v = *reinterpret_cast<const float4*>(xbase + r * FF + c);
        *reinterpret_cast<float4*>(&xs[r][c]) = v;
    }
    for (int i = tid; i < LL * FF; i += 256) pws[i >> 8][i & 255] = pw[i];
    for (int i = tid; i < FF * LL; i += 256) w1s[i >> 4][i & 15] = w1[i];
    b1s[tid] = b1[tid];
    w2s[tid] = w2[tid];
    __syncthreads();

    const int n = tid >> 4;
    const int l = tid & 15;
    ull a2 = 0ULL;
#pragma unroll 8
    for (int f2 = 0; f2 < FF / 2; f2++) {
        ull xv = *reinterpret_cast<const ull*>(&xs[n][f2 << 1]);
        ull wv = *reinterpret_cast<const ull*>(&pws[l][f2 << 1]);
        a2 = ffma2(xv, wv, a2);
    }
    float acc = hadd2(a2) + pb[l];

    __half zh = __float2half_rn(acc);
    g_zh[(size_t)(p0 + n) * LL + l] = zh;
    float az = __half2float(zh);
    zs[n][l] = acc;
    red[n][l] = az * az;
    __syncthreads();
    if (l == 0) {
        float s = 0.f;
#pragma unroll
        for (int j = 0; j < LL; j++) s += red[n][j];
        g_sqh[p0 + n] = s;
    }

    ull zp[8];
#pragma unroll
    for (int l2 = 0; l2 < 8; l2++) zp[l2] = *reinterpret_cast<const ull*>(&zs[n][l2 << 1]);

    float accum = 0.f;
#pragma unroll 4
    for (int i = 0; i < 16; i++) {
        const int f = l + 16 * i;
        ull d2 = 0ULL;
#pragma unroll
        for (int l2 = 0; l2 < 8; l2++) {
            ull wv = *reinterpret_cast<const ull*>(&w1s[f][l2 << 1]);
            d2 = ffma2(zp[l2], wv, d2);
        }
        float hv = hadd2(d2) + b1s[f];
        hv = fmaxf(hv, 0.f);
        accum = fmaf(hv, w2s[f], accum);
    }
#pragma unroll
    for (int o = 8; o > 0; o >>= 1) accum += __shfl_down_sync(0xffffffffu, accum, o, 16);
    if (l == 0) {
        float t = accum + b2[0];
        g_pi[p0 + n] = 1.0f / (1.0f + __expf(-t));
    }
}

// =====================================================================
// Kernel 2: symmetric K pass via HMMA Gram + wide fp16 ex2.
// K = ex2(min(2*log2e*G - log2e*(sq_n+sq_m), 0)) -- sq pre-scaled.
// Transpose via movmatrix (conflict-free packed STS.32).
// Grid: (NPAIRS, BB), 256 threads (8 warps x 16 rows).
// =====================================================================
#define GPW 12        // z smem pitch in words (24 halves)
#define KPW 68        // Kt pitch in words (136 halves)
#define KTPH 136      // KtT pitch in halves
#define O_ZN  0u
#define O_ZM  6144u
#define O_SQN 12288u
#define O_SQM 12800u
#define O_KT  13312u
#define O_KTT 48128u
#define O_RS  82944u
#define O_CS  83456u          // 8 x 132 floats
#define KK_SMEM 87680u

__global__ void __launch_bounds__(256, 2) k_K(void) {
    extern __shared__ __align__(16) unsigned char ks[];
    uint32_t* znW = reinterpret_cast<uint32_t*>(ks + O_ZN);
    uint32_t* zmW = reinterpret_cast<uint32_t*>(ks + O_ZM);
    float* sqnS = reinterpret_cast<float*>(ks + O_SQN);
    float* sqmS = reinterpret_cast<float*>(ks + O_SQM);
    uint32_t* ktW = reinterpret_cast<uint32_t*>(ks + O_KT);
    __half* ktT = reinterpret_cast<__half*>(ks + O_KTT);
    float* rsS = reinterpret_cast<float*>(ks + O_RS);
    float (*csS)[132] = reinterpret_cast<float(*)[132]>(ks + O_CS);

    const int tid = threadIdx.x;
    const int b = blockIdx.y;
    int p = blockIdx.x, ti = 0;
    while (p >= NT - ti) { p -= NT - ti; ti++; }
    const int tj = ti + p;
    const bool diag = (ti == tj);

    {
        const uint32_t* gn = reinterpret_cast<const uint32_t*>(
            g_zh + ((size_t)b * NN + ti * 128) * LL);
        const uint32_t* gm = reinterpret_cast<const uint32_t*>(
            g_zh + ((size_t)b * NN + tj * 128) * LL);
        for (int i = tid; i < 1024; i += 256) {
            znW[(i >> 3) * GPW + (i & 7)] = gn[i];
            zmW[(i >> 3) * GPW + (i & 7)] = gm[i];
        }
        const float* sqb = g_sqh + (size_t)b * NN;
        if (tid < 128) {
            sqnS[tid] = -NL2E * sqb[ti * 128 + tid];    // pre-scaled
            sqmS[tid] = -NL2E * sqb[tj * 128 + tid];
        }
    }
    __syncthreads();

    const int w = tid >> 5, lane = tid & 31;
    const int g = lane >> 2, q = lane & 3;
    const int r0 = w * 16 + g, r1 = r0 + 8;

    uint32_t af[4];
    af[0] = znW[r0 * GPW + q];
    af[1] = znW[r1 * GPW + q];
    af[2] = znW[r0 * GPW + q + 4];
    af[3] = znW[r1 * GPW + q + 4];

    float acc[16][4];
#pragma unroll
    for (int cf = 0; cf < 16; cf++) {
        acc[cf][0] = acc[cf][1] = acc[cf][2] = acc[cf][3] = 0.f;
        uint32_t bf[2];
        bf[0] = zmW[(cf * 8 + g) * GPW + q];
        bf[1] = zmW[(cf * 8 + g) * GPW + q + 4];
        mma16816(acc[cf], af, bf);
    }

    // elementwise: t = min(2*L2E*G + (sqn^+sqm^), 0); K = ex2(t) wide fp16
    const float sqr0 = sqnS[r0], sqr1 = sqnS[r1];
    const float TWOL2E = 2.0f * NL2E;
    float rs0 = 0.f, rs1 = 0.f;
#pragma unroll
    for (int cf = 0; cf < 16; cf++) {
        const int c0 = cf * 8 + 2 * q;
        float2 sqc = *reinterpret_cast<const float2*>(&sqmS[c0]);
        float t00 = fminf(fmaf(TWOL2E, acc[cf][0], sqr0 + sqc.x), 0.f);
        float t01 = fminf(fmaf(TWOL2E, acc[cf][1], sqr0 + sqc.y), 0.f);
        float t10 = fminf(fmaf(TWOL2E, acc[cf][2], sqr1 + sqc.x), 0.f);
        float t11 = fminf(fmaf(TWOL2E, acc[cf][3], sqr1 + sqc.y), 0.f);
        __half2 e0 = __floats2half2_rn(t00, t01);
        __half2 e1 = __floats2half2_rn(t10, t11);
        uint32_t h0 = ex2_f16x2(*reinterpret_cast<uint32_t*>(&e0));
        uint32_t h1 = ex2_f16x2(*reinterpret_cast<uint32_t*>(&e1));

        float2 f0 = __half22float2(*reinterpret_cast<__half2*>(&h0));
        float2 f1 = __half22float2(*reinterpret_cast<__half2*>(&h1));
        rs0 += f0.x + f0.y;
        rs1 += f1.x + f1.y;

        ktW[r0 * KPW + (c0 >> 1)] = h0;
        ktW[r1 * KPW + (c0 >> 1)] = h1;

        if (!diag) {
            // transpose via movmatrix: lane(g,q) -> K[w16(+8)+2q..+1][cf*8+g]
            uint32_t h0t = movmat_t(h0);
            uint32_t h1t = movmat_t(h1);
            *reinterpret_cast<uint32_t*>(&ktT[(cf * 8 + g) * KTPH + w * 16 + 2 * q]) = h0t;
            *reinterpret_cast<uint32_t*>(&ktT[(cf * 8 + g) * KTPH + w * 16 + 8 + 2 * q]) = h1t;

            float cs0 = f0.x + f1.x, cs1 = f0.y + f1.y;
#pragma unroll
            for (int o = 4; o <= 16; o <<= 1) {
                cs0 += __shfl_xor_sync(0xffffffffu, cs0, o);
                cs1 += __shfl_xor_sync(0xffffffffu, cs1, o);
            }
            if (g == 0) { csS[w][c0] = cs0; csS[w][c0 + 1] = cs1; }
        }
    }
    rs0 += __shfl_xor_sync(0xffffffffu, rs0, 1);
    rs0 += __shfl_xor_sync(0xffffffffu, rs0, 2);
    rs1 += __shfl_xor_sync(0xffffffffu, rs1, 1);
    rs1 += __shfl_xor_sync(0xffffffffu, rs1, 2);
    if (q == 0) { rsS[r0] = rs0; rsS[r1] = rs1; }
    __syncthreads();

    if (tid < 128)
        g_qpart[((size_t)b * NT + tj) * NN + ti * 128 + tid] = rsS[tid];
    if (!diag && tid < 128) {
        float s = 0.f;
#pragma unroll
        for (int ww = 0; ww < 8; ww++) s += csS[ww][tid];
        g_qpart[((size_t)b * NT + ti) * NN + tj * 128 + tid] = s;
    }

    uint32_t* gK1 = reinterpret_cast<uint32_t*>(
        g_K + ((size_t)(b * NN + ti * 128)) * NN + tj * 128);
    for (int i = tid; i < 128 * 64; i += 256)
        gK1[(size_t)(i >> 6) * (NN / 2) + (i & 63)] = ktW[(i >> 6) * KPW + (i & 63)];
    if (!diag) {
        uint32_t* gK2 = reinterpret_cast<uint32_t*>(
            g_K + ((size_t)(b * NN + tj * 128)) * NN + ti * 128);
        const uint32_t* ktTW = reinterpret_cast<const uint32_t*>(ktT);
        for (int i = tid; i < 128 * 64; i += 256)
            gK2[(size_t)(i >> 6) * (NN / 2) + (i & 63)] = ktTW[(i >> 6) * KPW + (i & 63)];
    }
}

// =====================================================================
// Kernel 3: q = sum partials ; c = pi/q ; y[f][m] = c[m]*x[m][f] fp16.
// =====================================================================
__global__ void __launch_bounds__(256) k_y(const float* __restrict__ x) {
    __shared__ float cs[TK];
    __shared__ uint32_t yt[256][33];

    const int tid = threadIdx.x;
    const int mt = blockIdx.x, b = blockIdx.y;
    const float* xb = x + ((size_t)b * NN + mt * TK) * FF;

    if (tid < TK) {
        const int lm = mt * TK + tid;
        float q = 0.f;
#pragma unroll
        for (int s = 0; s < NT; s++) q += g_qpart[((size_t)b * NT + s) * NN + lm];
        float c = g_pi[b * NN + lm] / q;
        g_c[b * NN + lm] = c;
        cs[tid] = c;
    }
    __syncthreads();

    const int f = tid;
#pragma unroll 8
    for (int j = 0; j < 32; j++) {
        float y0 = cs[2 * j]     * __ldg(xb + (size_t)(2 * j) * FF + f);
        float y1 = cs[2 * j + 1] * __ldg(xb + (size_t)(2 * j + 1) * FF + f);
        __half2 hv = __floats2half2_rn(y0, y1);
        yt[f][j] = *reinterpret_cast<uint32_t*>(&hv);
    }
    __syncthreads();
    uint32_t* gY = reinterpret_cast<uint32_t*>(g_y + ((size_t)b * FF * NN + mt * TK));
    for (int i = tid; i < 256 * 32; i += 256)
        gY[(size_t)(i >> 5) * (NN / 2) + (i & 31)] = yt[i >> 5][i & 31];
}

// =====================================================================
// Kernel 4: HMMA GEMM, 4-stage cp.async pipeline (distance 3), k-tile 32.
// =====================================================================
#define KAPITCH 40
#define ABYTES3 (64 * 80)
#define BBYTES3 (256 * 80)
#define STAGE (ABYTES3 + BBYTES3)     // 25600
#define NSTAGE 4
#define KTILES 64
#define OFF_C3  (NSTAGE * STAGE)      // 102400
#define OFF_RS3 (OFF_C3 + 512)        // 102912
#define OFF_SC3 (OFF_RS3 + 1024)      // 103936
#define SMEM3   (OFF_SC3 + 256)       // 104192

__global__ void __launch_bounds__(256, 2)
k_main(const float* __restrict__ x, float* __restrict__ out,
       const float* __restrict__ dtp) {
    extern __shared__ __align__(16) unsigned char sm[];
    const unsigned smb = smem_u32(sm);

    const int tid = threadIdx.x;
    const int nb = blockIdx.x, b = blockIdx.y;
    const int wid = tid >> 5, lane = tid & 31;
    const int g = lane >> 2, q = lane & 3;
    const int wm = wid & 1, wn = wid >> 1;

    const __half* Kg = g_K + (size_t)(b * NN + nb * 64) * NN;
    const __half* Yg = g_y + (size_t)b * FF * NN;
    const float* cg = g_c + (size_t)b * NN;

    auto fill = [&](int t, int st) {
        const unsigned aS = smb + st * STAGE;
        const unsigned bS = aS + ABYTES3;
        const __half* aG = Kg + t * 32;
        const __half* bG = Yg + t * 32;
        {
            const int i = tid;
            cp_async16s(aS + (i >> 2) * 80 + (i & 3) * 16,
                        aG + (size_t)(i >> 2) * NN + (i & 3) * 8);
        }
        for (int i = tid; i < 1024; i += 256)
            cp_async16s(bS + (i >> 2) * 80 + (i & 3) * 16,
                        bG + (size_t)(i >> 2) * NN + (i & 3) * 8);
        if (tid < 8)
            cp_async16s(smb + OFF_C3 + st * 128 + tid * 16, cg + t * 32 + tid * 4);
        cp_commit();
    };

    fill(0, 0);
    fill(1, 1);
    fill(2, 2);

    float acc[2][8][4];
#pragma unroll
    for (int mf = 0; mf < 2; mf++)
#pragma unroll
        for (int nf = 0; nf < 8; nf++)
#pragma unroll
            for (int k = 0; k < 4; k++) acc[mf][nf][k] = 0.f;
    float rs = 0.f;
    const int rn = tid & 63, qm = tid >> 6;

    const int a_row = wm * 32 + (lane & 15);
    const int a_kof = (lane >> 4) << 3;
    const int b_row = wn * 64 + (lane & 7) + ((lane >> 4) << 3);
    const int b_kof = ((lane >> 3) & 1) << 3;

    for (int t = 0; t < KTILES; t++) {
        const int st = t & 3;
        const int rem = KTILES - 1 - t;
        if (rem >= 2) cp_wait2(); else if (rem == 1) cp_wait1(); else cp_wait0();
        __syncthreads();
        if (t + 3 < KTILES) fill(t + 3, (t + 3) & 3);

        const unsigned KsA = smb + st * STAGE;
        const unsigned YsA = KsA + ABYTES3;
        const __half* Ks = reinterpret_cast<const __half*>(sm + st * STAGE);

        {
            const float* cP = reinterpret_cast<const float*>(sm + OFF_C3 + st * 128);
#pragma unroll
            for (int j = 0; j < 4; j++) {
                __half2 hv = *reinterpret_cast<const __half2*>(Ks + rn * KAPITCH + qm * 8 + 2 * j);
                float2 fv = __half22float2(hv);
                rs = fmaf(fv.x, cP[qm * 8 + 2 * j], rs);
                rs = fmaf(fv.y, cP[qm * 8 + 2 * j + 1], rs);
            }
        }

#pragma unroll
        for (int ksI = 0; ksI < 2; ksI++) {
            const int k0 = ksI * 16;
            uint32_t af[2][4];
#pragma unroll
            for (int mf = 0; mf < 2; mf++)
                ldsm4(af[mf], KsA + ((a_row + mf * 16) * KAPITCH + k0 + a_kof) * 2);
            uint32_t bf[8][2];
#pragma unroll
            for (int np = 0; np < 4; np++) {
                uint32_t r4[4];
                ldsm4(r4, YsA + ((b_row + np * 16) * KAPITCH + k0 + b_kof) * 2);
                bf[np * 2][0] = r4[0]; bf[np * 2][1] = r4[1];
                bf[np * 2 + 1][0] = r4[2]; bf[np * 2 + 1][1] = r4[3];
            }
#pragma unroll
            for (int mf = 0; mf < 2; mf++)
#pragma unroll
                for (int nf = 0; nf < 8; nf++)
                    mma16816(acc[mf][nf], af[mf], bf[nf]);
        }
    }

    __syncthreads();
    reinterpret_cast<float*>(sm + OFF_RS3)[rn * 4 + qm] = rs;
    __syncthreads();
    const float dtv = dtp[0];
    if (tid < 64) {
        const float* rp = reinterpret_cast<const float*>(sm + OFF_RS3) + tid * 4;
        float row = rp[0] + rp[1] + rp[2] + rp[3] + 1e-5f;
        reinterpret_cast<float*>(sm + OFF_SC3)[tid] = (dtv / EPSV) / row;
    }
    __syncthreads();

    const float omdt = 1.0f - dtv;
    const float* scS = reinterpret_cast<const float*>(sm + OFF_SC3);
#pragma unroll
    for (int mf = 0; mf < 2; mf++) {
        const int lr = wm * 32 + mf * 16 + g;
        const float sc1 = scS[lr], sc2 = scS[lr + 8];
        const size_t r1 = (size_t)(b * NN + nb * 64 + lr) * FF;
        const size_t r2 = r1 + (size_t)8 * FF;
#pragma unroll
        for (int nf = 0; nf < 8; nf++) {
            const int col = wn * 64 + nf * 8 + 2 * q;
            float2 x1 = *reinterpret_cast<const float2*>(x + r1 + col);
            float2 x2 = *reinterpret_cast<const float2*>(x + r2 + col);
            float2 o1, o2;
            o1.x = omdt * x1.x + sc1 * acc[mf][nf][0];
            o1.y = omdt * x1.y + sc1 * acc[mf][nf][1];
            o2.x = omdt * x2.x + sc2 * acc[mf][nf][2];
            o2.y = omdt * x2.y + sc2 * acc[mf][nf][3];
            *reinterpret_cast<float2*>(out + r1 + col) = o1;
            *reinterpret_cast<float2*>(out + r2 + col) = o2;
        }
    }
}

// =====================================================================
// launch
// =====================================================================
extern "C" void kernel_launch(void* const* d_in, const int* in_sizes, int n_in,
                              void* d_out, int out_size) {
    const float* x  = (const float*)d_in[0];
    const float* pw = (const float*)d_in[1];
    const float* pb = (const float*)d_in[2];
    const float* w1 = (const float*)d_in[3];
    const float* b1 = (const float*)d_in[4];
    const float* w2 = (const float*)d_in[5];
    const float* b2 = (const float*)d_in[6];
    const float* dt = (const float*)d_in[7];
    float* out = (float*)d_out;

    (void)in_sizes; (void)n_in; (void)out_size;

    const int npts = BB * NN;

    k_zpi<<<npts / 16, 256>>>(x, pw, pb, w1, b1, w2, b2);

    cudaFuncSetAttribute(k_K, cudaFuncAttributeMaxDynamicSharedMemorySize, (int)KK_SMEM);
    k_K<<<dim3(NPAIRS, BB), 256, KK_SMEM>>>();

    k_y<<<dim3(MTILES, BB), 256>>>(x);

    cudaFuncSetAttribute(k_main, cudaFuncAttributeMaxDynamicSharedMemorySize, (int)SMEM3);
    k_main<<<dim3(NN / 64, BB), 256, SMEM3>>>(x, out, dt);
}